// round 6
// baseline (speedup 1.0000x reference)
#include <cuda_runtime.h>
#include <cuda_fp16.h>
#include <stdint.h>

#define N_NODES 50000
#define E_EDGES 500000
#define R_REL 8
#define HID 128
#define NRSEG (N_NODES * R_REL)
#define NG 64
#define EPS_BN 1e-5f

typedef unsigned long long ull;

// ------------------------- device scratch ------------------------------------
__device__ __align__(16) float g_raw[N_NODES * HID];
__device__ __align__(16) float g_emb[N_NODES * HID];
__device__ __align__(16) float g_gemb[NG * HID];
__device__ __align__(16) __half g_xh[N_NODES * HID];
__device__ __align__(16) __half g_hh[N_NODES * HID];
__device__ __align__(16) __half g_embh[N_NODES * HID];
__device__ __align__(16) __half g_t1h[N_NODES * HID];
__device__ __align__(16) __half g_gembh[NG * HID];
__device__ __align__(16) __half g_w1hi[128 * 1152], g_w1lo[128 * 1152];
__device__ __align__(16) __half g_w2hi[128 * 1152], g_w2lo[128 * 1152];
__device__ __align__(16) __half g_w3hi[128 * 1152], g_w3lo[128 * 1152];
__device__ __align__(16) __half g_c1hi[128 * 256], g_c1lo[128 * 256];
__device__ __align__(16) __half g_c2hi[128 * 128], g_c2lo[128 * 128];

__device__ int   g_src32[E_EDGES];
__device__ int   g_segid[E_EDGES];
__device__ int   g_srcsorted[E_EDGES];
__device__ int   g_hist[NRSEG];          // static zero-init; scan3 re-zeroes
__device__ int   g_segstart[NRSEG + 1];
__device__ int   g_cursor[NRSEG];
__device__ float g_inv[NRSEG];
__device__ int   g_batch32[N_NODES];
__device__ int   g_gstart[NG + 1];
__device__ float g_scores[N_NODES];
__device__ float g_attn[N_NODES];
__device__ float g_colstats[2 * HID];
__device__ float g_bnscale[HID];
__device__ float g_bnshift[HID];
__device__ unsigned g_maxkey;
__device__ float g_sumexp;
__device__ int   g_is64;
__device__ int   g_bsums[512];

// ------------------------- helpers ------------------------------------------
__device__ __forceinline__ float lrelu(float x) { return x > 0.f ? x : 0.1f * x; }

__device__ __forceinline__ unsigned enc_f(float f) {
    unsigned b = __float_as_uint(f);
    return (b & 0x80000000u) ? ~b : (b | 0x80000000u);
}
__device__ __forceinline__ float dec_f(unsigned k) {
    unsigned b = (k & 0x80000000u) ? (k & 0x7FFFFFFFu) : ~k;
    return __uint_as_float(b);
}
__device__ __forceinline__ uint32_t smem_u32(const void* p) {
    return (uint32_t)__cvta_generic_to_shared(p);
}
__device__ __forceinline__ uint32_t pk_h2(float a, float b) {
    __half2 h = __float22half2_rn(make_float2(a, b));
    return *(uint32_t*)&h;
}

// ------------------------- mma.sync / ldmatrix / cp.async --------------------
__device__ __forceinline__ void cp16(uint32_t dst, const void* src, uint32_t srcsz) {
    asm volatile("cp.async.ca.shared.global [%0], [%1], 16, %2;"
        :: "r"(dst), "l"(src), "r"(srcsz) : "memory");
}
__device__ __forceinline__ void cp_commit() {
    asm volatile("cp.async.commit_group;" ::: "memory");
}
__device__ __forceinline__ void cp_wait0() {
    asm volatile("cp.async.wait_group 0;" ::: "memory");
}
__device__ __forceinline__ void ldm4(uint32_t* r, uint32_t addr) {
    asm volatile("ldmatrix.sync.aligned.m8n8.x4.shared.b16 {%0,%1,%2,%3}, [%4];"
        : "=r"(r[0]), "=r"(r[1]), "=r"(r[2]), "=r"(r[3]) : "r"(addr));
}
__device__ __forceinline__ void mma16816(float* c, const uint32_t* a, const uint32_t* b) {
    asm volatile("mma.sync.aligned.m16n8k16.row.col.f32.f16.f16.f32 "
        "{%0,%1,%2,%3}, {%4,%5,%6,%7}, {%8,%9}, {%0,%1,%2,%3};"
        : "+f"(c[0]), "+f"(c[1]), "+f"(c[2]), "+f"(c[3])
        : "r"(a[0]), "r"(a[1]), "r"(a[2]), "r"(a[3]), "r"(b[0]), "r"(b[1]));
}

// ------------------------- dtype detection ----------------------------------
__global__ void k_detect(const ull* __restrict__ ei) {
    __shared__ unsigned s_is32;
    if (threadIdx.x == 0) s_is32 = 0;
    __syncthreads();
    ull m = 0;
    for (int i = threadIdx.x; i < 1024; i += 256) { ull v = ei[i]; m = v > m ? v : m; }
    if (m >= (1ull << 32)) atomicOr(&s_is32, 1u);
    __syncthreads();
    if (threadIdx.x == 0) g_is64 = s_is32 ? 0 : 1;
}

// ------------------------- edge preprocessing -------------------------------
__global__ void k_edge_prep(const void* __restrict__ ei, const void* __restrict__ et,
                            const void* __restrict__ bt) {
    int e = blockIdx.x * blockDim.x + threadIdx.x;
    int is64 = g_is64;
    if (e < E_EDGES) {
        int src, dst, ty;
        if (is64) {
            const long long* p = (const long long*)ei;
            src = (int)p[e]; dst = (int)p[E_EDGES + e];
            ty = (int)((const long long*)et)[e];
        } else {
            const int* p = (const int*)ei;
            src = p[e]; dst = p[E_EDGES + e];
            ty = ((const int*)et)[e];
        }
        g_src32[e] = src;
        int s = dst * R_REL + ty;
        g_segid[e] = s;
        atomicAdd(&g_hist[s], 1);
    }
    if (e < N_NODES)
        g_batch32[e] = is64 ? (int)((const long long*)bt)[e] : ((const int*)bt)[e];
}

__global__ void k_scan1() {
    __shared__ int sd[256];
    int t = threadIdx.x;
    int base = blockIdx.x * 1024 + t * 4;
    int v0 = 0, v1 = 0, v2 = 0, v3 = 0;
    if (base + 0 < NRSEG) v0 = g_hist[base + 0];
    if (base + 1 < NRSEG) v1 = g_hist[base + 1];
    if (base + 2 < NRSEG) v2 = g_hist[base + 2];
    if (base + 3 < NRSEG) v3 = g_hist[base + 3];
    int ts = v0 + v1 + v2 + v3;
    sd[t] = ts; __syncthreads();
    for (int off = 1; off < 256; off <<= 1) {
        int x = (t >= off) ? sd[t - off] : 0;
        __syncthreads();
        sd[t] += x;
        __syncthreads();
    }
    int ex = sd[t] - ts;
    if (base + 0 < NRSEG) g_segstart[base + 0] = ex;
    ex += v0; if (base + 1 < NRSEG) g_segstart[base + 1] = ex;
    ex += v1; if (base + 2 < NRSEG) g_segstart[base + 2] = ex;
    ex += v2; if (base + 3 < NRSEG) g_segstart[base + 3] = ex;
    if (t == 255) g_bsums[blockIdx.x] = sd[255];
}

__global__ void k_scan2(int nb) {
    __shared__ int sd[512];
    int t = threadIdx.x;
    int v = (t < nb) ? g_bsums[t] : 0;
    sd[t] = v; __syncthreads();
    for (int off = 1; off < 512; off <<= 1) {
        int x = (t >= off) ? sd[t - off] : 0;
        __syncthreads();
        sd[t] += x;
        __syncthreads();
    }
    if (t < nb) g_bsums[t] = sd[t] - v;
}

__global__ void k_scan3() {
    int i = blockIdx.x * blockDim.x + threadIdx.x;
    if (i < NRSEG) {
        int v = g_segstart[i] + g_bsums[i >> 10];
        g_segstart[i] = v;
        g_cursor[i] = v;
        int c = g_hist[i];
        g_inv[i] = 1.0f / (float)(c > 0 ? c : 1);
        g_hist[i] = 0;            // self-clear for next graph replay
    }
    if (i == 0) g_segstart[NRSEG] = E_EDGES;
}

__global__ void k_permute() {
    int e = blockIdx.x * blockDim.x + threadIdx.x;
    if (e < E_EDGES) {
        int s = g_segid[e];
        int pos = atomicAdd(&g_cursor[s], 1);
        g_srcsorted[pos] = g_src32[e];
    }
}

// ------------------------- fp32 -> fp16 --------------------------------------
__global__ void k_tohalf(const float* __restrict__ src, __half* __restrict__ dst, int total4) {
    int i = blockIdx.x * blockDim.x + threadIdx.x;
    if (i < total4) {
        float4 v = ((const float4*)src)[i];
        uint2 o;
        o.x = pk_h2(v.x, v.y);
        o.y = pk_h2(v.z, v.w);
        ((uint2*)dst)[i] = o;
    }
}

// ------------------------- weight prep (fp16 hi/lo split) --------------------
__global__ void k_wprep(const float* __restrict__ W, const float* __restrict__ root,
                        __half* __restrict__ bh, __half* __restrict__ bl) {
    int idx = blockIdx.x * blockDim.x + threadIdx.x;
    if (idx < 128 * 1152) {
        int c = idx / 1152, k = idx % 1152;
        float v = (k < 1024) ? W[((k >> 7) * 128 + (k & 127)) * 128 + c]
                             : root[(k - 1024) * 128 + c];
        __half h = __float2half_rn(v);
        bh[idx] = h;
        bl[idx] = __float2half_rn(v - __half2float(h));
    }
}

template <int K>
__global__ void k_cprep(const float* __restrict__ C, __half* __restrict__ bh,
                        __half* __restrict__ bl) {
    int idx = blockIdx.x * blockDim.x + threadIdx.x;
    if (idx < 128 * K) {
        int c = idx / K, k = idx % K;
        float v = C[k * 128 + c];
        __half h = __float2half_rn(v);
        bh[idx] = h;
        bl[idx] = __float2half_rn(v - __half2float(h));
    }
}

// ------------------------- mma.sync GEMM (fused aggregation) -----------------
// 128x128 CTA tile, 256 thr, warp grid 4(M)x2(N), warp tile 32x64.
// D = A*Bhi^T + A*Blo^T (fp32 acc).
// MODE 0/1: A-part for k<1024 is aggregated ON THE FLY from h (L2 gather);
//           k>=1024 is the root part (h itself). MODE 0 adds BN stats->raw.
//           MODE 1 -> emb fp32 + embh.
// MODE 2: A=[embh|gembh[batch]], lrelu, out=t1h. MODE 3: row-norm -> outf.
#define BKC 32
#define ROWB 80          // smem bytes per tile row (32 fp16 + 16B pad)
#define TILE_B 10240     // 128 * 80
#define BUF_B 30720      // 3 tiles (A, Bhi, Blo)
#define CP 132           // staging row stride (floats)
#define SEG_OFF (2 * BUF_B)          // 61440
#define INV_OFF (SEG_OFF + 4112)     // after 1025 ints (padded)
#define DSMB (INV_OFF + 4096 + 48)   // 69696

template <int MODE, int KT>
__global__ void __launch_bounds__(256, 2) k_mgemm(
    const __half* __restrict__ A, const __half* __restrict__ A2,
    const int* __restrict__ batch,
    const __half* __restrict__ Bhi, const __half* __restrict__ Blo,
    const float* __restrict__ bias,
    float* __restrict__ outf, __half* __restrict__ oh) {
    constexpr int NCH = KT / BKC;
    extern __shared__ __align__(16) char dsm[];
    __shared__ float s_bias[128];
    __shared__ float s_stat[256];

    int tid = threadIdx.x;
    int bm = blockIdx.x * 128;
    int wid = tid >> 5, lane = tid & 31;
    int mo = (wid & 3) * 32;
    int no = (wid >> 2) * 64;
    uint32_t sbase = smem_u32(dsm);
    int* s_segs = (int*)(dsm + SEG_OFF);
    float* s_inv = (float*)(dsm + INV_OFF);

    if (tid < 128) s_bias[tid] = bias[tid];
    if (MODE == 0) { s_stat[tid] = 0.f; }

    // preload per-CTA segment tables (1024 segments + end sentinel)
    if (MODE <= 1) {
        int sb8 = bm * 8;
        for (int j = tid; j < 1025; j += 256) {
            int gi = sb8 + j; if (gi > NRSEG) gi = NRSEG;
            s_segs[j] = g_segstart[gi];
        }
        for (int j = tid; j < 1024; j += 256) {
            int gi = sb8 + j; if (gi >= NRSEG) gi = NRSEG - 1;
            s_inv[j] = g_inv[gi];
        }
    }
    __syncthreads();

    float acc[2][8][4];
#pragma unroll
    for (int mi = 0; mi < 2; mi++)
#pragma unroll
        for (int j = 0; j < 8; j++)
#pragma unroll
            for (int q = 0; q < 4; q++) acc[mi][j][q] = 0.f;

    auto loadChunk = [&](int i) {
        int b = i & 1;
        uint32_t sb = sbase + b * BUF_B;
        int k0 = i * BKC;
        // B tiles via cp.async (always)
#pragma unroll
        for (int it = 0; it < 2; it++) {
            int idx = it * 256 + tid;
            int row = idx >> 2, seg = idx & 3;
            uint32_t db = sb + TILE_B + (uint32_t)(row * ROWB + seg * 16);
            cp16(db, Bhi + (size_t)row * KT + k0 + seg * 8, 16u);
            cp16(db + TILE_B, Blo + (size_t)row * KT + k0 + seg * 8, 16u);
        }
        if (MODE <= 1 && k0 < 1024) {
            cp_commit();
            // fused aggregation: 4 threads per segment, 2 passes of 64 rows
            int r = k0 >> 7, cq = k0 & 127;
            int cs = tid & 3;
            const __half* hbase = A + cq + cs * 8;
            char* abuf = dsm + b * BUF_B;
#pragma unroll
            for (int p = 0; p < 2; p++) {
                int srow = p * 64 + (tid >> 2);
                int lseg = srow * 8 + r;
                int beg = s_segs[lseg], end = s_segs[lseg + 1];
                float a0 = 0.f, a1 = 0.f, a2 = 0.f, a3 = 0.f;
                float a4 = 0.f, a5 = 0.f, a6 = 0.f, a7 = 0.f;
                for (int e = beg; e < end; e++) {
                    int src = g_srcsorted[e];
                    uint4 v = *(const uint4*)(hbase + (size_t)src * 128);
                    float2 f0 = __half22float2(*(__half2*)&v.x);
                    float2 f1 = __half22float2(*(__half2*)&v.y);
                    float2 f2 = __half22float2(*(__half2*)&v.z);
                    float2 f3 = __half22float2(*(__half2*)&v.w);
                    a0 += f0.x; a1 += f0.y; a2 += f1.x; a3 += f1.y;
                    a4 += f2.x; a5 += f2.y; a6 += f3.x; a7 += f3.y;
                }
                float inv = s_inv[lseg];
                uint4 o;
                o.x = pk_h2(a0 * inv, a1 * inv);
                o.y = pk_h2(a2 * inv, a3 * inv);
                o.z = pk_h2(a4 * inv, a5 * inv);
                o.w = pk_h2(a6 * inv, a7 * inv);
                *(uint4*)(abuf + srow * ROWB + cs * 16) = o;
            }
        } else {
            // A rows via cp.async
#pragma unroll
            for (int it = 0; it < 2; it++) {
                int idx = it * 256 + tid;
                int row = idx >> 2, seg = idx & 3;
                int n = bm + row;
                bool v = (n < N_NODES);
                int nn = v ? n : 0;
                const __half* pa;
                if (MODE <= 1) {
                    pa = A + (size_t)nn * 128 + (k0 - 1024);
                } else if (MODE == 2) {
                    if (k0 < 128) pa = A + (size_t)nn * 128 + k0;
                    else {
                        int g = v ? batch[nn] : 0;
                        pa = A2 + (size_t)g * 128 + (k0 - 128);
                    }
                } else {
                    pa = A + (size_t)nn * 128 + k0;
                }
                cp16(sb + (uint32_t)(row * ROWB + seg * 16), pa + seg * 8, v ? 16u : 0u);
            }
            cp_commit();
        }
    };

    loadChunk(0);
    for (int i = 0; i < NCH; i++) {
        cp_wait0();
        __syncthreads();
        if (i + 1 < NCH) loadChunk(i + 1);
        uint32_t ab = sbase + (uint32_t)((i & 1) * BUF_B);
#pragma unroll
        for (int kk = 0; kk < 2; kk++) {
            uint32_t a[2][4];
#pragma unroll
            for (int mi = 0; mi < 2; mi++) {
                uint32_t r = (uint32_t)(mo + mi * 16 + (lane & 15));
                uint32_t c = (uint32_t)(kk * 16 + (lane >> 4) * 8);
                ldm4(a[mi], ab + r * ROWB + c * 2);
            }
#pragma unroll
            for (int jp = 0; jp < 4; jp++) {
                uint32_t r = (uint32_t)(no + jp * 16 + (lane & 15));
                uint32_t c = (uint32_t)(kk * 16 + (lane >> 4) * 8);
                uint32_t bd = ab + TILE_B + r * ROWB + c * 2;
                uint32_t t[4], u[4];
                ldm4(t, bd);
                ldm4(u, bd + TILE_B);
                uint32_t bh0[2] = {t[0], t[2]}, bh1[2] = {t[1], t[3]};
                uint32_t bl0[2] = {u[0], u[2]}, bl1[2] = {u[1], u[3]};
#pragma unroll
                for (int mi = 0; mi < 2; mi++) {
                    mma16816(acc[mi][jp * 2 + 0], a[mi], bh0);
                    mma16816(acc[mi][jp * 2 + 0], a[mi], bl0);
                    mma16816(acc[mi][jp * 2 + 1], a[mi], bh1);
                    mma16816(acc[mi][jp * 2 + 1], a[mi], bl1);
                }
            }
        }
        __syncthreads();
    }

    // ---- stage accumulators to smem ----
    float* Cs = (float*)dsm;
#pragma unroll
    for (int mi = 0; mi < 2; mi++)
#pragma unroll
        for (int j = 0; j < 8; j++) {
            int r0 = mo + mi * 16 + (lane >> 2);
            int col = no + j * 8 + (lane & 3) * 2;
            *(float2*)&Cs[r0 * CP + col] = make_float2(acc[mi][j][0], acc[mi][j][1]);
            *(float2*)&Cs[(r0 + 8) * CP + col] = make_float2(acc[mi][j][2], acc[mi][j][3]);
        }
    __syncthreads();

    // ---- per-row epilogue: threads 0..127 own row tid ----
    if (tid < 128) {
        int n = bm + tid;
        bool valid = (n < N_NODES);
        const float* crow = &Cs[tid * CP];

        if (MODE == 3) {
            float ss = 0.f;
#pragma unroll 8
            for (int c = 0; c < 128; c++) {
                float v = crow[c] + s_bias[c];
                ss += v * v;
            }
            float sc = 1.f / fmaxf(sqrtf(ss), 1e-12f);
            if (valid) {
#pragma unroll
                for (int c4 = 0; c4 < 32; c4++) {
                    float4 o;
                    o.x = (crow[c4 * 4 + 0] + s_bias[c4 * 4 + 0]) * sc;
                    o.y = (crow[c4 * 4 + 1] + s_bias[c4 * 4 + 1]) * sc;
                    o.z = (crow[c4 * 4 + 2] + s_bias[c4 * 4 + 2]) * sc;
                    o.w = (crow[c4 * 4 + 3] + s_bias[c4 * 4 + 3]) * sc;
                    *(float4*)&outf[(size_t)n * 128 + c4 * 4] = o;
                }
            }
        } else {
#pragma unroll
            for (int cb = 0; cb < 4; cb++) {
                float vf[32];
#pragma unroll
                for (int j = 0; j < 32; j++) {
                    float v = crow[cb * 32 + j] + s_bias[cb * 32 + j];
                    if (MODE == 2) v = lrelu(v);
                    vf[j] = v;
                }
                if (MODE == 0) {
#pragma unroll
                    for (int j = 0; j < 32; j++) {
                        float a_ = valid ? vf[j] : 0.f;
                        float q_ = valid ? vf[j] * vf[j] : 0.f;
#pragma unroll
                        for (int off = 16; off > 0; off >>= 1) {
                            a_ += __shfl_xor_sync(0xffffffffu, a_, off);
                            q_ += __shfl_xor_sync(0xffffffffu, q_, off);
                        }
                        if ((tid & 31) == 0) {
                            atomicAdd(&s_stat[cb * 32 + j], a_);
                            atomicAdd(&s_stat[128 + cb * 32 + j], q_);
                        }
                    }
                }
                if (valid) {
                    if (MODE == 0 || MODE == 1) {
#pragma unroll
                        for (int j4 = 0; j4 < 8; j4++)
                            *(float4*)&outf[(size_t)n * 128 + cb * 32 + j4 * 4] =
                                make_float4(vf[j4 * 4], vf[j4 * 4 + 1], vf[j4 * 4 + 2], vf[j4 * 4 + 3]);
                    }
                    if (MODE == 1 || MODE == 2) {
                        uint32_t* ph = (uint32_t*)(oh + (size_t)n * 128 + cb * 32);
#pragma unroll
                        for (int j2 = 0; j2 < 16; j2++)
                            ph[j2] = pk_h2(vf[j2 * 2], vf[j2 * 2 + 1]);
                    }
                }
            }
        }
    }
    __syncthreads();
    if (MODE == 0 && tid < 256) atomicAdd(&g_colstats[tid], s_stat[tid]);
}

// ------------------------- BN ------------------------------------------------
__global__ void k_zero_small() {
    int t = threadIdx.x;
    if (t < 256) g_colstats[t] = 0.f;
    if (t == 0) { g_maxkey = 0u; g_sumexp = 0.f; }
}

__global__ void k_bnfin(const float* __restrict__ gamma, const float* __restrict__ beta) {
    int c = threadIdx.x;
    if (c < HID) {
        float inv_n = 1.f / (float)N_NODES;
        float mu = g_colstats[c] * inv_n;
        float var = fmaxf(g_colstats[HID + c] * inv_n - mu * mu, 0.f);
        float sc = gamma[c] * rsqrtf(var + EPS_BN);
        g_bnscale[c] = sc;
        g_bnshift[c] = beta[c] - mu * sc;
    }
}

__global__ void k_bnapply() {
    int i = blockIdx.x * blockDim.x + threadIdx.x;
    if (i < N_NODES * 32) {
        float4 v = ((const float4*)g_raw)[i];
        int c4 = i & 31;
        float4 sc = ((const float4*)g_bnscale)[c4];
        float4 sh = ((const float4*)g_bnshift)[c4];
        float ox = lrelu(v.x * sc.x + sh.x);
        float oy = lrelu(v.y * sc.y + sh.y);
        float oz = lrelu(v.z * sc.z + sh.z);
        float ow = lrelu(v.w * sc.w + sh.w);
        uint2 o;
        o.x = pk_h2(ox, oy);
        o.y = pk_h2(oz, ow);
        ((uint2*)g_hh)[i] = o;
    }
}

// ------------------------- attention ------------------------------------------
__global__ void __launch_bounds__(256) k_scores(const float* __restrict__ A1,
                                                const float* __restrict__ a1,
                                                const float* __restrict__ A2,
                                                const float* __restrict__ a2v) {
    __shared__ float sA1[HID * 64];
    __shared__ float sA2[64];
    __shared__ float sa1[64];
    __shared__ float se[8][HID];
    __shared__ unsigned s_bmax;
    int tid = threadIdx.x;
    for (int i = tid; i < HID * 64; i += 256) sA1[i] = A1[i];
    if (tid < 64) { sA2[tid] = A2[tid]; sa1[tid] = a1[tid]; }
    if (tid == 0) s_bmax = 0u;
    __syncthreads();
    int w = tid >> 5, lane = tid & 31;
    unsigned localmax = 0u;
    float a2s = a2v[0];
    for (int n = blockIdx.x * 8 + w; n < N_NODES; n += gridDim.x * 8) {
        for (int i = lane; i < HID; i += 32) se[w][i] = g_emb[(size_t)n * HID + i];
        __syncwarp();
        float acc0 = 0.f, acc1 = 0.f;
#pragma unroll 8
        for (int k = 0; k < HID; k++) {
            float e = se[w][k];
            acc0 = fmaf(e, sA1[k * 64 + lane], acc0);
            acc1 = fmaf(e, sA1[k * 64 + lane + 32], acc1);
        }
        acc0 = lrelu(acc0 + sa1[lane]);
        acc1 = lrelu(acc1 + sa1[lane + 32]);
        float part = acc0 * sA2[lane] + acc1 * sA2[lane + 32];
#pragma unroll
        for (int off = 16; off > 0; off >>= 1) part += __shfl_down_sync(0xFFFFFFFFu, part, off);
        if (lane == 0) {
            float s = part + a2s;
            g_scores[n] = s;
            unsigned k = enc_f(s);
            localmax = k > localmax ? k : localmax;
        }
        __syncwarp();
    }
    if (lane == 0 && localmax) atomicMax(&s_bmax, localmax);
    __syncthreads();
    if (tid == 0) atomicMax(&g_maxkey, s_bmax);
}

__global__ void k_sumexp() {
    __shared__ float sred[256];
    int n = blockIdx.x * blockDim.x + threadIdx.x;
    float gmax = dec_f(g_maxkey);
    float v = (n < N_NODES) ? expf(g_scores[n] - gmax) : 0.f;
    sred[threadIdx.x] = v;
    __syncthreads();
    for (int off = 128; off > 0; off >>= 1) {
        if (threadIdx.x < off) sred[threadIdx.x] += sred[threadIdx.x + off];
        __syncthreads();
    }
    if (threadIdx.x == 0) atomicAdd(&g_sumexp, sred[0]);
}

__global__ void k_attn() {
    int n = blockIdx.x * blockDim.x + threadIdx.x;
    if (n < N_NODES) {
        float gmax = dec_f(g_maxkey);
        g_attn[n] = expf(g_scores[n] - gmax) / g_sumexp;
    }
}

__global__ void k_gbounds() {
    int i = blockIdx.x * blockDim.x + threadIdx.x;
    if (i <= N_NODES) {
        int cur = (i < N_NODES) ? g_batch32[i] : NG;
        int prev = (i == 0) ? -1 : g_batch32[i - 1];
        for (int g = prev + 1; g <= cur && g <= NG; g++) g_gstart[g] = i;
    }
}

__global__ void k_pool() {
    int g = blockIdx.x, c = threadIdx.x;
    float acc = 0.f;
    int b = g_gstart[g], e = g_gstart[g + 1];
    for (int n = b; n < e; n++) acc += g_emb[(size_t)n * HID + c] * g_attn[n];
    g_gemb[g * HID + c] = acc;
}

// ------------------------- host launcher --------------------------------------
extern "C" void kernel_launch(void* const* d_in, const int* in_sizes, int n_in,
                              void* d_out, int out_size) {
    const float* x     = (const float*)d_in[0];
    const void*  ei    = d_in[1];
    const void*  et    = d_in[2];
    const void*  bt    = d_in[3];
    const float* W1    = (const float*)d_in[4];
    const float* root1 = (const float*)d_in[5];
    const float* b1    = (const float*)d_in[6];
    const float* W2    = (const float*)d_in[7];
    const float* root2 = (const float*)d_in[8];
    const float* b2    = (const float*)d_in[9];
    const float* W3    = (const float*)d_in[10];
    const float* root3 = (const float*)d_in[11];
    const float* b3    = (const float*)d_in[12];
    const float* g1    = (const float*)d_in[13];
    const float* beta1 = (const float*)d_in[14];
    const float* g2    = (const float*)d_in[15];
    const float* beta2 = (const float*)d_in[16];
    const float* A1    = (const float*)d_in[17];
    const float* a1    = (const float*)d_in[18];
    const float* A2    = (const float*)d_in[19];
    const float* a2    = (const float*)d_in[20];
    const float* C1    = (const float*)d_in[21];
    const float* c1    = (const float*)d_in[22];
    const float* C2    = (const float*)d_in[23];
    const float* c2    = (const float*)d_in[24];
    float* out = (float*)d_out;

    void* p;
    cudaGetSymbolAddress(&p, g_raw);    float* raw  = (float*)p;
    cudaGetSymbolAddress(&p, g_emb);    float* emb  = (float*)p;
    cudaGetSymbolAddress(&p, g_gemb);   float* gemb = (float*)p;
    cudaGetSymbolAddress(&p, g_xh);     __half* xh = (__half*)p;
    cudaGetSymbolAddress(&p, g_hh);     __half* hh = (__half*)p;
    cudaGetSymbolAddress(&p, g_embh);   __half* embh = (__half*)p;
    cudaGetSymbolAddress(&p, g_t1h);    __half* t1h = (__half*)p;
    cudaGetSymbolAddress(&p, g_gembh);  __half* gembh = (__half*)p;
    cudaGetSymbolAddress(&p, g_w1hi);   __half* w1hi = (__half*)p;
    cudaGetSymbolAddress(&p, g_w1lo);   __half* w1lo = (__half*)p;
    cudaGetSymbolAddress(&p, g_w2hi);   __half* w2hi = (__half*)p;
    cudaGetSymbolAddress(&p, g_w2lo);   __half* w2lo = (__half*)p;
    cudaGetSymbolAddress(&p, g_w3hi);   __half* w3hi = (__half*)p;
    cudaGetSymbolAddress(&p, g_w3lo);   __half* w3lo = (__half*)p;
    cudaGetSymbolAddress(&p, g_c1hi);   __half* c1hi = (__half*)p;
    cudaGetSymbolAddress(&p, g_c1lo);   __half* c1lo = (__half*)p;
    cudaGetSymbolAddress(&p, g_c2hi);   __half* c2hi = (__half*)p;
    cudaGetSymbolAddress(&p, g_c2lo);   __half* c2lo = (__half*)p;
    cudaGetSymbolAddress(&p, g_batch32); int* batch32 = (int*)p;

    const int DSM = DSMB;
    cudaFuncSetAttribute(k_mgemm<0, 1152>, cudaFuncAttributeMaxDynamicSharedMemorySize, DSM);
    cudaFuncSetAttribute(k_mgemm<1, 1152>, cudaFuncAttributeMaxDynamicSharedMemorySize, DSM);
    cudaFuncSetAttribute(k_mgemm<2, 256>,  cudaFuncAttributeMaxDynamicSharedMemorySize, DSM);
    cudaFuncSetAttribute(k_mgemm<3, 128>,  cudaFuncAttributeMaxDynamicSharedMemorySize, DSM);

    const int NB1 = (NRSEG + 1023) / 1024;

    k_detect<<<1, 256>>>((const ull*)ei);
    k_edge_prep<<<(E_EDGES + 255) / 256, 256>>>(ei, et, bt);
    k_scan1<<<NB1, 256>>>();
    k_scan2<<<1, 512>>>(NB1);
    k_scan3<<<(NRSEG + 255) / 256, 256>>>();
    k_permute<<<(E_EDGES + 255) / 256, 256>>>();

    k_wprep<<<(128 * 1152 + 255) / 256, 256>>>(W1, root1, w1hi, w1lo);
    k_wprep<<<(128 * 1152 + 255) / 256, 256>>>(W2, root2, w2hi, w2lo);
    k_wprep<<<(128 * 1152 + 255) / 256, 256>>>(W3, root3, w3hi, w3lo);
    k_cprep<256><<<(128 * 256 + 255) / 256, 256>>>(C1, c1hi, c1lo);
    k_cprep<128><<<(128 * 128 + 255) / 256, 256>>>(C2, c2hi, c2lo);
    k_tohalf<<<(N_NODES * 32 + 255) / 256, 256>>>(x, xh, N_NODES * 32);

    const int GB = (N_NODES + 127) / 128;   // 391

    // layer 1 (fused agg from xh)
    k_zero_small<<<1, 256>>>();
    k_mgemm<0, 1152><<<GB, 256, DSM>>>(xh, nullptr, nullptr, w1hi, w1lo, b1, raw, nullptr);
    k_bnfin<<<1, 128>>>(g1, beta1);
    k_bnapply<<<(N_NODES * 32 + 255) / 256, 256>>>();

    // layer 2 (fused agg from hh)
    k_zero_small<<<1, 256>>>();
    k_mgemm<0, 1152><<<GB, 256, DSM>>>(hh, nullptr, nullptr, w2hi, w2lo, b2, raw, nullptr);
    k_bnfin<<<1, 128>>>(g2, beta2);
    k_bnapply<<<(N_NODES * 32 + 255) / 256, 256>>>();

    // layer 3 (fused agg from hh)
    k_mgemm<1, 1152><<<GB, 256, DSM>>>(hh, nullptr, nullptr, w3hi, w3lo, b3, emb, embh);

    // attention pooling
    k_zero_small<<<1, 256>>>();
    k_scores<<<512, 256>>>(A1, a1, A2, a2);
    k_sumexp<<<(N_NODES + 255) / 256, 256>>>();
    k_attn<<<(N_NODES + 255) / 256, 256>>>();
    k_gbounds<<<(N_NODES + 256) / 256, 256>>>();
    k_pool<<<NG, 128>>>();
    k_tohalf<<<(NG * 32 + 255) / 256, 256>>>(gemb, gembh, NG * 32);

    // combiner MLP + row normalize
    k_mgemm<2, 256><<<GB, 256, DSM>>>(embh, gembh, batch32, c1hi, c1lo, c1, nullptr, t1h);
    k_mgemm<3, 128><<<GB, 256, DSM>>>(t1h, nullptr, nullptr, c2hi, c2lo, c2, out, nullptr);

    (void)in_sizes; (void)n_in; (void)out_size;
}

// round 7
// speedup vs baseline: 1.2176x; 1.2176x over previous
#include <cuda_runtime.h>
#include <cuda_fp16.h>
#include <stdint.h>

#define N_NODES 50000
#define E_EDGES 500000
#define R_REL 8
#define HID 128
#define NRSEG (N_NODES * R_REL)
#define NG 64
#define EPS_BN 1e-5f

typedef unsigned long long ull;

// ------------------------- device scratch ------------------------------------
__device__ __align__(16) __half g_aggh[(size_t)NRSEG * 128];    // 102.4MB
__device__ __align__(16) float g_raw[N_NODES * HID];
__device__ __align__(16) float g_emb[N_NODES * HID];
__device__ __align__(16) __half g_xh[N_NODES * HID];
__device__ __align__(16) __half g_hh[N_NODES * HID];
__device__ __align__(16) __half g_embh[N_NODES * HID];
__device__ __align__(16) __half g_t1h[N_NODES * HID];
__device__ __align__(16) __half g_gembh[NG * HID];
__device__ __align__(16) __half g_w1hi[128 * 1152];
__device__ __align__(16) __half g_w2hi[128 * 1152];
__device__ __align__(16) __half g_w3hi[128 * 1152];
__device__ __align__(16) __half g_c1hi[128 * 256], g_c1lo[128 * 256];
__device__ __align__(16) __half g_c2hi[128 * 128], g_c2lo[128 * 128];

__device__ int   g_src32[E_EDGES];
__device__ int   g_segid[E_EDGES];
__device__ int   g_srcsorted[E_EDGES];
__device__ int   g_hist[NRSEG];          // static zero-init; scan3 re-zeroes
__device__ int   g_segstart[NRSEG + 1];
__device__ int   g_cursor[NRSEG];
__device__ float g_inv[NRSEG];
__device__ int   g_batch32[N_NODES];
__device__ int   g_gstart[NG + 1];
__device__ float g_scores[N_NODES];
__device__ float g_colstats[2 * HID];
__device__ float g_bnscale[HID];
__device__ float g_bnshift[HID];
__device__ unsigned g_maxkey;
__device__ float g_sumexp;
__device__ int   g_is64;
__device__ int   g_bsums[512];

// ------------------------- helpers ------------------------------------------
__device__ __forceinline__ float lrelu(float x) { return x > 0.f ? x : 0.1f * x; }

__device__ __forceinline__ unsigned enc_f(float f) {
    unsigned b = __float_as_uint(f);
    return (b & 0x80000000u) ? ~b : (b | 0x80000000u);
}
__device__ __forceinline__ float dec_f(unsigned k) {
    unsigned b = (k & 0x80000000u) ? (k & 0x7FFFFFFFu) : ~k;
    return __uint_as_float(b);
}
__device__ __forceinline__ uint32_t smem_u32(const void* p) {
    return (uint32_t)__cvta_generic_to_shared(p);
}
__device__ __forceinline__ uint32_t pk_h2(float a, float b) {
    __half2 h = __float22half2_rn(make_float2(a, b));
    return *(uint32_t*)&h;
}

// ------------------------- mma.sync / ldmatrix / cp.async --------------------
__device__ __forceinline__ void cp16(uint32_t dst, const void* src, uint32_t srcsz) {
    asm volatile("cp.async.ca.shared.global [%0], [%1], 16, %2;"
        :: "r"(dst), "l"(src), "r"(srcsz) : "memory");
}
__device__ __forceinline__ void cp_commit() {
    asm volatile("cp.async.commit_group;" ::: "memory");
}
__device__ __forceinline__ void cp_wait0() {
    asm volatile("cp.async.wait_group 0;" ::: "memory");
}
__device__ __forceinline__ void cp_wait1() {
    asm volatile("cp.async.wait_group 1;" ::: "memory");
}
__device__ __forceinline__ void ldm4(uint32_t* r, uint32_t addr) {
    asm volatile("ldmatrix.sync.aligned.m8n8.x4.shared.b16 {%0,%1,%2,%3}, [%4];"
        : "=r"(r[0]), "=r"(r[1]), "=r"(r[2]), "=r"(r[3]) : "r"(addr));
}
__device__ __forceinline__ void mma16816(float* c, const uint32_t* a, const uint32_t* b) {
    asm volatile("mma.sync.aligned.m16n8k16.row.col.f32.f16.f16.f32 "
        "{%0,%1,%2,%3}, {%4,%5,%6,%7}, {%8,%9}, {%0,%1,%2,%3};"
        : "+f"(c[0]), "+f"(c[1]), "+f"(c[2]), "+f"(c[3])
        : "r"(a[0]), "r"(a[1]), "r"(a[2]), "r"(a[3]), "r"(b[0]), "r"(b[1]));
}

// ------------------------- dtype detection ----------------------------------
__global__ void k_detect(const ull* __restrict__ ei) {
    __shared__ unsigned s_is32;
    if (threadIdx.x == 0) s_is32 = 0;
    __syncthreads();
    ull m = 0;
    for (int i = threadIdx.x; i < 1024; i += 256) { ull v = ei[i]; m = v > m ? v : m; }
    if (m >= (1ull << 32)) atomicOr(&s_is32, 1u);
    __syncthreads();
    if (threadIdx.x == 0) g_is64 = s_is32 ? 0 : 1;
}

// ------------------------- edge preprocessing -------------------------------
__global__ void k_edge_prep(const void* __restrict__ ei, const void* __restrict__ et,
                            const void* __restrict__ bt) {
    int e = blockIdx.x * blockDim.x + threadIdx.x;
    int is64 = g_is64;
    if (e < E_EDGES) {
        int src, dst, ty;
        if (is64) {
            const long long* p = (const long long*)ei;
            src = (int)p[e]; dst = (int)p[E_EDGES + e];
            ty = (int)((const long long*)et)[e];
        } else {
            const int* p = (const int*)ei;
            src = p[e]; dst = p[E_EDGES + e];
            ty = ((const int*)et)[e];
        }
        g_src32[e] = src;
        int s = dst * R_REL + ty;
        g_segid[e] = s;
        atomicAdd(&g_hist[s], 1);
    }
    if (e < N_NODES)
        g_batch32[e] = is64 ? (int)((const long long*)bt)[e] : ((const int*)bt)[e];
}

__global__ void k_scan1() {
    __shared__ int sd[256];
    int t = threadIdx.x;
    int base = blockIdx.x * 1024 + t * 4;
    int v0 = 0, v1 = 0, v2 = 0, v3 = 0;
    if (base + 0 < NRSEG) v0 = g_hist[base + 0];
    if (base + 1 < NRSEG) v1 = g_hist[base + 1];
    if (base + 2 < NRSEG) v2 = g_hist[base + 2];
    if (base + 3 < NRSEG) v3 = g_hist[base + 3];
    int ts = v0 + v1 + v2 + v3;
    sd[t] = ts; __syncthreads();
    for (int off = 1; off < 256; off <<= 1) {
        int x = (t >= off) ? sd[t - off] : 0;
        __syncthreads();
        sd[t] += x;
        __syncthreads();
    }
    int ex = sd[t] - ts;
    if (base + 0 < NRSEG) g_segstart[base + 0] = ex;
    ex += v0; if (base + 1 < NRSEG) g_segstart[base + 1] = ex;
    ex += v1; if (base + 2 < NRSEG) g_segstart[base + 2] = ex;
    ex += v2; if (base + 3 < NRSEG) g_segstart[base + 3] = ex;
    if (t == 255) g_bsums[blockIdx.x] = sd[255];
}

__global__ void k_scan2(int nb) {
    __shared__ int sd[512];
    int t = threadIdx.x;
    int v = (t < nb) ? g_bsums[t] : 0;
    sd[t] = v; __syncthreads();
    for (int off = 1; off < 512; off <<= 1) {
        int x = (t >= off) ? sd[t - off] : 0;
        __syncthreads();
        sd[t] += x;
        __syncthreads();
    }
    if (t < nb) g_bsums[t] = sd[t] - v;
}

__global__ void k_scan3() {
    int i = blockIdx.x * blockDim.x + threadIdx.x;
    if (i < NRSEG) {
        int v = g_segstart[i] + g_bsums[i >> 10];
        g_segstart[i] = v;
        g_cursor[i] = v;
        int c = g_hist[i];
        g_inv[i] = 1.0f / (float)(c > 0 ? c : 1);
        g_hist[i] = 0;            // self-clear for next graph replay
    }
    if (i < 2 * HID) g_colstats[i] = 0.f;
    if (i == 0) { g_segstart[NRSEG] = E_EDGES; g_maxkey = 0u; g_sumexp = 0.f; }
}

__global__ void k_permute() {
    int e = blockIdx.x * blockDim.x + threadIdx.x;
    if (e < E_EDGES) {
        int s = g_segid[e];
        int pos = atomicAdd(&g_cursor[s], 1);
        g_srcsorted[pos] = g_src32[e];
    }
}

// ------------------------- aggregation (gathers fp16, sums fp32) ------------
__global__ void __launch_bounds__(256) k_aggregate(const __half* __restrict__ hsrc) {
    int warp = (blockIdx.x * blockDim.x + threadIdx.x) >> 5;
    int lane = threadIdx.x & 31;
    if (warp >= NRSEG) return;
    int beg = g_segstart[warp], end = g_segstart[warp + 1];
    float ax = 0.f, ay = 0.f, az = 0.f, aw = 0.f;
    for (int e = beg; e < end; e++) {
        int s = g_srcsorted[e];
        uint2 v = ((const uint2*)(hsrc + (size_t)s * 128))[lane];
        float2 f0 = __half22float2(*(__half2*)&v.x);
        float2 f1 = __half22float2(*(__half2*)&v.y);
        ax += f0.x; ay += f0.y; az += f1.x; aw += f1.y;
    }
    float inv = g_inv[warp];
    uint2 o;
    o.x = pk_h2(ax * inv, ay * inv);
    o.y = pk_h2(az * inv, aw * inv);
    ((uint2*)g_aggh)[(size_t)warp * 32 + lane] = o;
}

// ------------------------- fp32 -> fp16 --------------------------------------
__global__ void k_tohalf(const float* __restrict__ src, __half* __restrict__ dst, int total4) {
    int i = blockIdx.x * blockDim.x + threadIdx.x;
    if (i < total4) {
        float4 v = ((const float4*)src)[i];
        uint2 o;
        o.x = pk_h2(v.x, v.y);
        o.y = pk_h2(v.z, v.w);
        ((uint2*)dst)[i] = o;
    }
}

// ------------------------- weight prep ---------------------------------------
__global__ void k_wprep(const float* __restrict__ W, const float* __restrict__ root,
                        __half* __restrict__ bh) {
    int idx = blockIdx.x * blockDim.x + threadIdx.x;
    if (idx < 128 * 1152) {
        int c = idx / 1152, k = idx % 1152;
        float v = (k < 1024) ? W[((k >> 7) * 128 + (k & 127)) * 128 + c]
                             : root[(k - 1024) * 128 + c];
        bh[idx] = __float2half_rn(v);
    }
}

template <int K>
__global__ void k_cprep(const float* __restrict__ C, __half* __restrict__ bh,
                        __half* __restrict__ bl) {
    int idx = blockIdx.x * blockDim.x + threadIdx.x;
    if (idx < 128 * K) {
        int c = idx / K, k = idx % K;
        float v = C[k * 128 + c];
        __half h = __float2half_rn(v);
        bh[idx] = h;
        bl[idx] = __float2half_rn(v - __half2float(h));
    }
}

// ------------------------- mma.sync GEMM -------------------------------------
// 128x128 CTA tile, 256 thr, warp grid 4(M)x2(N), warp tile 32x64.
// SPLIT=0: D = A*Bhi^T (1 product, 3-stage pipeline)
// SPLIT=1: D = A*Bhi^T + A*Blo^T (2 products, 2-stage)
// MODE 0: +BN stats, out=raw. MODE 1: out=emb fp32 + embh.
// MODE 2: A=[embh|gembh[batch]], lrelu, out=t1h. MODE 3: row-norm -> outf.
#define BKC 32
#define ROWB 80          // smem bytes per tile row (32 fp16 + 16B pad)
#define TILE_B 10240     // 128 * 80
#define CP 132           // staging row stride (floats)
#define DSMB (128 * CP * 4)   // 67584

template <int MODE, int KT, int SPLIT>
__global__ void __launch_bounds__(256, 2) k_mgemm(
    const __half* __restrict__ A, const __half* __restrict__ A2,
    const int* __restrict__ batch,
    const __half* __restrict__ Bhi, const __half* __restrict__ Blo,
    const float* __restrict__ bias,
    float* __restrict__ outf, __half* __restrict__ oh) {
    constexpr int NCH = KT / BKC;
    constexpr int STAGES = SPLIT ? 2 : 3;
    constexpr int SBUF = (SPLIT ? 3 : 2) * TILE_B;
    extern __shared__ __align__(16) char dsm[];
    __shared__ float s_bias[128];
    __shared__ float s_stat[256];

    int tid = threadIdx.x;
    int bm = blockIdx.x * 128;
    int wid = tid >> 5, lane = tid & 31;
    int mo = (wid & 3) * 32;
    int no = (wid >> 2) * 64;
    uint32_t sbase = smem_u32(dsm);

    if (tid < 128) s_bias[tid] = bias[tid];
    if (MODE == 0) s_stat[tid] = 0.f;

    float acc[2][8][4];
#pragma unroll
    for (int mi = 0; mi < 2; mi++)
#pragma unroll
        for (int j = 0; j < 8; j++)
#pragma unroll
            for (int q = 0; q < 4; q++) acc[mi][j][q] = 0.f;

    auto loadChunk = [&](int i) {
        int st = i % STAGES;
        uint32_t sb = sbase + (uint32_t)(st * SBUF);
        int k0 = i * BKC;
#pragma unroll
        for (int it = 0; it < 2; it++) {
            int idx = it * 256 + tid;
            int row = idx >> 2, seg = idx & 3;
            int n = bm + row;
            bool v = (n < N_NODES);
            int nn = v ? n : 0;
            const __half* pa;
            if (MODE <= 1) {
                pa = (k0 < 1024) ? A + (size_t)nn * 1024 + k0
                                 : A2 + (size_t)nn * 128 + (k0 - 1024);
            } else if (MODE == 2) {
                if (k0 < 128) pa = A + (size_t)nn * 128 + k0;
                else {
                    int g = v ? batch[nn] : 0;
                    pa = A2 + (size_t)g * 128 + (k0 - 128);
                }
            } else {
                pa = A + (size_t)nn * 128 + k0;
            }
            cp16(sb + (uint32_t)(row * ROWB + seg * 16), pa + seg * 8, v ? 16u : 0u);
            uint32_t db = sb + TILE_B + (uint32_t)(row * ROWB + seg * 16);
            cp16(db, Bhi + (size_t)row * KT + k0 + seg * 8, 16u);
            if (SPLIT)
                cp16(db + TILE_B, Blo + (size_t)row * KT + k0 + seg * 8, 16u);
        }
        cp_commit();
    };

    loadChunk(0);
    if (STAGES == 3 && NCH > 1) loadChunk(1);
    for (int i = 0; i < NCH; i++) {
        if (STAGES == 3) cp_wait1(); else cp_wait0();
        __syncthreads();
        if (STAGES == 3) { if (i + 2 < NCH) loadChunk(i + 2); }
        else             { if (i + 1 < NCH) loadChunk(i + 1); }
        uint32_t ab = sbase + (uint32_t)((i % STAGES) * SBUF);
#pragma unroll
        for (int kk = 0; kk < 2; kk++) {
            uint32_t a[2][4];
#pragma unroll
            for (int mi = 0; mi < 2; mi++) {
                uint32_t r = (uint32_t)(mo + mi * 16 + (lane & 15));
                uint32_t c = (uint32_t)(kk * 16 + (lane >> 4) * 8);
                ldm4(a[mi], ab + r * ROWB + c * 2);
            }
#pragma unroll
            for (int jp = 0; jp < 4; jp++) {
                uint32_t r = (uint32_t)(no + jp * 16 + (lane & 15));
                uint32_t c = (uint32_t)(kk * 16 + (lane >> 4) * 8);
                uint32_t bd = ab + TILE_B + r * ROWB + c * 2;
                uint32_t t[4];
                ldm4(t, bd);
                uint32_t bh0[2] = {t[0], t[2]}, bh1[2] = {t[1], t[3]};
#pragma unroll
                for (int mi = 0; mi < 2; mi++) {
                    mma16816(acc[mi][jp * 2 + 0], a[mi], bh0);
                    mma16816(acc[mi][jp * 2 + 1], a[mi], bh1);
                }
                if (SPLIT) {
                    uint32_t u[4];
                    ldm4(u, bd + TILE_B);
                    uint32_t bl0[2] = {u[0], u[2]}, bl1[2] = {u[1], u[3]};
#pragma unroll
                    for (int mi = 0; mi < 2; mi++) {
                        mma16816(acc[mi][jp * 2 + 0], a[mi], bl0);
                        mma16816(acc[mi][jp * 2 + 1], a[mi], bl1);
                    }
                }
            }
        }
        __syncthreads();
    }

    // ---- stage accumulators to smem ----
    float* Cs = (float*)dsm;
#pragma unroll
    for (int mi = 0; mi < 2; mi++)
#pragma unroll
        for (int j = 0; j < 8; j++) {
            int r0 = mo + mi * 16 + (lane >> 2);
            int col = no + j * 8 + (lane & 3) * 2;
            *(float2*)&Cs[r0 * CP + col] = make_float2(acc[mi][j][0], acc[mi][j][1]);
            *(float2*)&Cs[(r0 + 8) * CP + col] = make_float2(acc[mi][j][2], acc[mi][j][3]);
        }
    __syncthreads();

    // ---- per-row epilogue: threads 0..127 own row tid ----
    if (tid < 128) {
        int n = bm + tid;
        bool valid = (n < N_NODES);
        const float* crow = &Cs[tid * CP];

        if (MODE == 3) {
            float ss = 0.f;
#pragma unroll 8
            for (int c = 0; c < 128; c++) {
                float v = crow[c] + s_bias[c];
                ss += v * v;
            }
            float sc = 1.f / fmaxf(sqrtf(ss), 1e-12f);
            if (valid) {
#pragma unroll
                for (int c4 = 0; c4 < 32; c4++) {
                    float4 o;
                    o.x = (crow[c4 * 4 + 0] + s_bias[c4 * 4 + 0]) * sc;
                    o.y = (crow[c4 * 4 + 1] + s_bias[c4 * 4 + 1]) * sc;
                    o.z = (crow[c4 * 4 + 2] + s_bias[c4 * 4 + 2]) * sc;
                    o.w = (crow[c4 * 4 + 3] + s_bias[c4 * 4 + 3]) * sc;
                    *(float4*)&outf[(size_t)n * 128 + c4 * 4] = o;
                }
            }
        } else {
#pragma unroll
            for (int cb = 0; cb < 4; cb++) {
                float vf[32];
#pragma unroll
                for (int j = 0; j < 32; j++) {
                    float v = crow[cb * 32 + j] + s_bias[cb * 32 + j];
                    if (MODE == 2) v = lrelu(v);
                    vf[j] = v;
                }
                if (MODE == 0) {
#pragma unroll
                    for (int j = 0; j < 32; j++) {
                        float a_ = valid ? vf[j] : 0.f;
                        float q_ = valid ? vf[j] * vf[j] : 0.f;
#pragma unroll
                        for (int off = 16; off > 0; off >>= 1) {
                            a_ += __shfl_xor_sync(0xffffffffu, a_, off);
                            q_ += __shfl_xor_sync(0xffffffffu, q_, off);
                        }
                        if ((tid & 31) == 0) {
                            atomicAdd(&s_stat[cb * 32 + j], a_);
                            atomicAdd(&s_stat[128 + cb * 32 + j], q_);
                        }
                    }
                }
                if (valid) {
                    if (MODE == 0 || MODE == 1) {
#pragma unroll
                        for (int j4 = 0; j4 < 8; j4++)
                            *(float4*)&outf[(size_t)n * 128 + cb * 32 + j4 * 4] =
                                make_float4(vf[j4 * 4], vf[j4 * 4 + 1], vf[j4 * 4 + 2], vf[j4 * 4 + 3]);
                    }
                    if (MODE == 1 || MODE == 2) {
                        uint32_t* ph = (uint32_t*)(oh + (size_t)n * 128 + cb * 32);
#pragma unroll
                        for (int j2 = 0; j2 < 16; j2++)
                            ph[j2] = pk_h2(vf[j2 * 2], vf[j2 * 2 + 1]);
                    }
                }
            }
        }
    }
    __syncthreads();
    if (MODE == 0 && tid < 256) atomicAdd(&g_colstats[tid], s_stat[tid]);
}

// ------------------------- BN ------------------------------------------------
__global__ void k_bnfin(const float* __restrict__ gamma, const float* __restrict__ beta) {
    int c = threadIdx.x;
    if (c < HID) {
        float inv_n = 1.f / (float)N_NODES;
        float mu = g_colstats[c] * inv_n;
        float var = fmaxf(g_colstats[HID + c] * inv_n - mu * mu, 0.f);
        float sc = gamma[c] * rsqrtf(var + EPS_BN);
        g_bnscale[c] = sc;
        g_bnshift[c] = beta[c] - mu * sc;
        g_colstats[c] = 0.f;           // re-arm for next layer / replay
        g_colstats[HID + c] = 0.f;
    }
}

__global__ void k_bnapply() {
    int i = blockIdx.x * blockDim.x + threadIdx.x;
    if (i < N_NODES * 32) {
        float4 v = ((const float4*)g_raw)[i];
        int c4 = i & 31;
        float4 sc = ((const float4*)g_bnscale)[c4];
        float4 sh = ((const float4*)g_bnshift)[c4];
        float ox = lrelu(v.x * sc.x + sh.x);
        float oy = lrelu(v.y * sc.y + sh.y);
        float oz = lrelu(v.z * sc.z + sh.z);
        float ow = lrelu(v.w * sc.w + sh.w);
        uint2 o;
        o.x = pk_h2(ox, oy);
        o.y = pk_h2(oz, ow);
        ((uint2*)g_hh)[i] = o;
    }
}

// ------------------------- attention ------------------------------------------
__global__ void __launch_bounds__(256) k_scores(const float* __restrict__ A1,
                                                const float* __restrict__ a1,
                                                const float* __restrict__ A2,
                                                const float* __restrict__ a2v) {
    __shared__ float sA1[HID * 64];
    __shared__ float sA2[64];
    __shared__ float sa1[64];
    __shared__ float se[8][HID];
    __shared__ unsigned s_bmax;
    int tid = threadIdx.x;
    for (int i = tid; i < HID * 64; i += 256) sA1[i] = A1[i];
    if (tid < 64) { sA2[tid] = A2[tid]; sa1[tid] = a1[tid]; }
    if (tid == 0) s_bmax = 0u;
    __syncthreads();
    int w = tid >> 5, lane = tid & 31;
    unsigned localmax = 0u;
    float a2s = a2v[0];
    for (int n = blockIdx.x * 8 + w; n < N_NODES; n += gridDim.x * 8) {
        for (int i = lane; i < HID; i += 32) se[w][i] = g_emb[(size_t)n * HID + i];
        __syncwarp();
        float acc0 = 0.f, acc1 = 0.f;
#pragma unroll 8
        for (int k = 0; k < HID; k++) {
            float e = se[w][k];
            acc0 = fmaf(e, sA1[k * 64 + lane], acc0);
            acc1 = fmaf(e, sA1[k * 64 + lane + 32], acc1);
        }
        acc0 = lrelu(acc0 + sa1[lane]);
        acc1 = lrelu(acc1 + sa1[lane + 32]);
        float part = acc0 * sA2[lane] + acc1 * sA2[lane + 32];
#pragma unroll
        for (int off = 16; off > 0; off >>= 1) part += __shfl_down_sync(0xFFFFFFFFu, part, off);
        if (lane == 0) {
            float s = part + a2s;
            g_scores[n] = s;
            unsigned k = enc_f(s);
            localmax = k > localmax ? k : localmax;
        }
        __syncwarp();
    }
    if (lane == 0 && localmax) atomicMax(&s_bmax, localmax);
    __syncthreads();
    if (tid == 0) atomicMax(&g_maxkey, s_bmax);
}

__global__ void k_sumexp() {
    __shared__ float sred[256];
    int n = blockIdx.x * blockDim.x + threadIdx.x;
    float gmax = dec_f(g_maxkey);
    float v = (n < N_NODES) ? expf(g_scores[n] - gmax) : 0.f;
    sred[threadIdx.x] = v;
    __syncthreads();
    for (int off = 128; off > 0; off >>= 1) {
        if (threadIdx.x < off) sred[threadIdx.x] += sred[threadIdx.x + off];
        __syncthreads();
    }
    if (threadIdx.x == 0) atomicAdd(&g_sumexp, sred[0]);
}

__global__ void k_gbounds() {
    int i = blockIdx.x * blockDim.x + threadIdx.x;
    if (i <= N_NODES) {
        int cur = (i < N_NODES) ? g_batch32[i] : NG;
        int prev = (i == 0) ? -1 : g_batch32[i - 1];
        for (int g = prev + 1; g <= cur && g <= NG; g++) g_gstart[g] = i;
    }
}

// pool with fused softmax weights + fp16 output
__global__ void k_pool() {
    int g = blockIdx.x, c = threadIdx.x;
    float gmax = dec_f(g_maxkey);
    float invs = 1.f / g_sumexp;
    float acc = 0.f;
    int b = g_gstart[g], e = g_gstart[g + 1];
    for (int n = b; n < e; n++)
        acc += g_emb[(size_t)n * HID + c] * (expf(g_scores[n] - gmax) * invs);
    g_gembh[g * HID + c] = __float2half_rn(acc);
}

// ------------------------- host launcher --------------------------------------
extern "C" void kernel_launch(void* const* d_in, const int* in_sizes, int n_in,
                              void* d_out, int out_size) {
    const float* x     = (const float*)d_in[0];
    const void*  ei    = d_in[1];
    const void*  et    = d_in[2];
    const void*  bt    = d_in[3];
    const float* W1    = (const float*)d_in[4];
    const float* root1 = (const float*)d_in[5];
    const float* b1    = (const float*)d_in[6];
    const float* W2    = (const float*)d_in[7];
    const float* root2 = (const float*)d_in[8];
    const float* b2    = (const float*)d_in[9];
    const float* W3    = (const float*)d_in[10];
    const float* root3 = (const float*)d_in[11];
    const float* b3    = (const float*)d_in[12];
    const float* g1    = (const float*)d_in[13];
    const float* beta1 = (const float*)d_in[14];
    const float* g2    = (const float*)d_in[15];
    const float* beta2 = (const float*)d_in[16];
    const float* A1    = (const float*)d_in[17];
    const float* a1    = (const float*)d_in[18];
    const float* A2    = (const float*)d_in[19];
    const float* a2    = (const float*)d_in[20];
    const float* C1    = (const float*)d_in[21];
    const float* c1    = (const float*)d_in[22];
    const float* C2    = (const float*)d_in[23];
    const float* c2    = (const float*)d_in[24];
    float* out = (float*)d_out;

    void* p;
    cudaGetSymbolAddress(&p, g_aggh);   __half* aggh = (__half*)p;
    cudaGetSymbolAddress(&p, g_raw);    float* raw  = (float*)p;
    cudaGetSymbolAddress(&p, g_emb);    float* emb  = (float*)p;
    cudaGetSymbolAddress(&p, g_xh);     __half* xh = (__half*)p;
    cudaGetSymbolAddress(&p, g_hh);     __half* hh = (__half*)p;
    cudaGetSymbolAddress(&p, g_embh);   __half* embh = (__half*)p;
    cudaGetSymbolAddress(&p, g_t1h);    __half* t1h = (__half*)p;
    cudaGetSymbolAddress(&p, g_gembh);  __half* gembh = (__half*)p;
    cudaGetSymbolAddress(&p, g_w1hi);   __half* w1hi = (__half*)p;
    cudaGetSymbolAddress(&p, g_w2hi);   __half* w2hi = (__half*)p;
    cudaGetSymbolAddress(&p, g_w3hi);   __half* w3hi = (__half*)p;
    cudaGetSymbolAddress(&p, g_c1hi);   __half* c1hi = (__half*)p;
    cudaGetSymbolAddress(&p, g_c1lo);   __half* c1lo = (__half*)p;
    cudaGetSymbolAddress(&p, g_c2hi);   __half* c2hi = (__half*)p;
    cudaGetSymbolAddress(&p, g_c2lo);   __half* c2lo = (__half*)p;
    cudaGetSymbolAddress(&p, g_batch32); int* batch32 = (int*)p;

    const int DSM = DSMB;
    cudaFuncSetAttribute(k_mgemm<0, 1152, 0>, cudaFuncAttributeMaxDynamicSharedMemorySize, DSM);
    cudaFuncSetAttribute(k_mgemm<1, 1152, 0>, cudaFuncAttributeMaxDynamicSharedMemorySize, DSM);
    cudaFuncSetAttribute(k_mgemm<2, 256, 1>,  cudaFuncAttributeMaxDynamicSharedMemorySize, DSM);
    cudaFuncSetAttribute(k_mgemm<3, 128, 1>,  cudaFuncAttributeMaxDynamicSharedMemorySize, DSM);

    const int NB1 = (NRSEG + 1023) / 1024;

    k_detect<<<1, 256>>>((const ull*)ei);
    k_edge_prep<<<(E_EDGES + 255) / 256, 256>>>(ei, et, bt);
    k_scan1<<<NB1, 256>>>();
    k_scan2<<<1, 512>>>(NB1);
    k_scan3<<<(NRSEG + 255) / 256, 256>>>();
    k_permute<<<(E_EDGES + 255) / 256, 256>>>();

    k_wprep<<<(128 * 1152 + 255) / 256, 256>>>(W1, root1, w1hi);
    k_wprep<<<(128 * 1152 + 255) / 256, 256>>>(W2, root2, w2hi);
    k_wprep<<<(128 * 1152 + 255) / 256, 256>>>(W3, root3, w3hi);
    k_cprep<256><<<(128 * 256 + 255) / 256, 256>>>(C1, c1hi, c1lo);
    k_cprep<128><<<(128 * 128 + 255) / 256, 256>>>(C2, c2hi, c2lo);
    k_tohalf<<<(N_NODES * 32 + 255) / 256, 256>>>(x, xh, N_NODES * 32);

    const int GB = (N_NODES + 127) / 128;   // 391
    const int AGG_BLOCKS = NRSEG / 8;       // 50000

    // layer 1
    k_aggregate<<<AGG_BLOCKS, 256>>>(xh);
    k_mgemm<0, 1152, 0><<<GB, 256, DSM>>>(aggh, xh, nullptr, w1hi, nullptr, b1, raw, nullptr);
    k_bnfin<<<1, 128>>>(g1, beta1);
    k_bnapply<<<(N_NODES * 32 + 255) / 256, 256>>>();

    // layer 2
    k_aggregate<<<AGG_BLOCKS, 256>>>(hh);
    k_mgemm<0, 1152, 0><<<GB, 256, DSM>>>(aggh, hh, nullptr, w2hi, nullptr, b2, raw, nullptr);
    k_bnfin<<<1, 128>>>(g2, beta2);
    k_bnapply<<<(N_NODES * 32 + 255) / 256, 256>>>();

    // layer 3
    k_aggregate<<<AGG_BLOCKS, 256>>>(hh);
    k_mgemm<1, 1152, 0><<<GB, 256, DSM>>>(aggh, hh, nullptr, w3hi, nullptr, b3, emb, embh);

    // attention pooling (attn + fp16 convert fused into k_pool)
    k_scores<<<512, 256>>>(A1, a1, A2, a2);
    k_sumexp<<<(N_NODES + 255) / 256, 256>>>();
    k_gbounds<<<(N_NODES + 256) / 256, 256>>>();
    k_pool<<<NG, 128>>>();

    // combiner MLP (keep 2-product split for error margin) + row normalize
    k_mgemm<2, 256, 1><<<GB, 256, DSM>>>(embh, gembh, batch32, c1hi, c1lo, c1, nullptr, t1h);
    k_mgemm<3, 128, 1><<<GB, 256, DSM>>>(t1h, nullptr, nullptr, c2hi, c2lo, c2, out, nullptr);

    (void)in_sizes; (void)n_in; (void)out_size;
}

// round 8
// speedup vs baseline: 1.4848x; 1.2195x over previous
#include <cuda_runtime.h>
#include <cuda_fp16.h>
#include <stdint.h>

#define N_NODES 50000
#define E_EDGES 500000
#define R_REL 8
#define HID 128
#define NRSEG (N_NODES * R_REL)
#define NG 64
#define EPS_BN 1e-5f

typedef unsigned long long ull;

// ------------------------- device scratch ------------------------------------
__device__ __align__(16) __half g_aggh[(size_t)NRSEG * 128];    // 102.4MB
__device__ __align__(16) float g_raw[N_NODES * HID];
__device__ __align__(16) float g_emb[N_NODES * HID];
__device__ __align__(16) __half g_xh[N_NODES * HID];
__device__ __align__(16) __half g_hh[N_NODES * HID];
__device__ __align__(16) __half g_embh[N_NODES * HID];
__device__ __align__(16) __half g_t1h[N_NODES * HID];
__device__ __align__(16) __half g_gembh[NG * HID];
__device__ __align__(16) __half g_w1hi[128 * 1152];
__device__ __align__(16) __half g_w2hi[128 * 1152];
__device__ __align__(16) __half g_w3hi[128 * 1152];
__device__ __align__(16) __half g_c1hi[128 * 256], g_c1lo[128 * 256];
__device__ __align__(16) __half g_c2hi[128 * 128], g_c2lo[128 * 128];
__device__ __align__(16) __half g_a1thi[64 * 128], g_a1tlo[64 * 128];  // A1^T split

__device__ int   g_src32[E_EDGES];
__device__ int   g_segid[E_EDGES];
__device__ int   g_srcsorted[E_EDGES];
__device__ int   g_hist[NRSEG];          // static zero-init; scan3 re-zeroes
__device__ int   g_segstart[NRSEG + 1];
__device__ int   g_cursor[NRSEG];
__device__ float g_inv[NRSEG];
__device__ int   g_batch32[N_NODES];
__device__ int   g_gstart[NG + 1];
__device__ float g_scores[N_NODES];
__device__ float g_colstats[2 * HID];
__device__ float g_bnscale[HID];
__device__ float g_bnshift[HID];
__device__ unsigned g_maxkey;
__device__ float g_sumexp;
__device__ int   g_bsums[512];

// ------------------------- helpers ------------------------------------------
__device__ __forceinline__ float lrelu(float x) { return x > 0.f ? x : 0.1f * x; }

__device__ __forceinline__ unsigned enc_f(float f) {
    unsigned b = __float_as_uint(f);
    return (b & 0x80000000u) ? ~b : (b | 0x80000000u);
}
__device__ __forceinline__ float dec_f(unsigned k) {
    unsigned b = (k & 0x80000000u) ? (k & 0x7FFFFFFFu) : ~k;
    return __uint_as_float(b);
}
__device__ __forceinline__ uint32_t smem_u32(const void* p) {
    return (uint32_t)__cvta_generic_to_shared(p);
}
__device__ __forceinline__ uint32_t pk_h2(float a, float b) {
    __half2 h = __float22half2_rn(make_float2(a, b));
    return *(uint32_t*)&h;
}

// ------------------------- mma.sync / ldmatrix / cp.async --------------------
__device__ __forceinline__ void cp16(uint32_t dst, const void* src, uint32_t srcsz) {
    asm volatile("cp.async.ca.shared.global [%0], [%1], 16, %2;"
        :: "r"(dst), "l"(src), "r"(srcsz) : "memory");
}
__device__ __forceinline__ void cp_commit() {
    asm volatile("cp.async.commit_group;" ::: "memory");
}
template <int N>
__device__ __forceinline__ void cp_wait() {
    asm volatile("cp.async.wait_group %0;" :: "n"(N) : "memory");
}
__device__ __forceinline__ void ldm4(uint32_t* r, uint32_t addr) {
    asm volatile("ldmatrix.sync.aligned.m8n8.x4.shared.b16 {%0,%1,%2,%3}, [%4];"
        : "=r"(r[0]), "=r"(r[1]), "=r"(r[2]), "=r"(r[3]) : "r"(addr));
}
__device__ __forceinline__ void mma16816(float* c, const uint32_t* a, const uint32_t* b) {
    asm volatile("mma.sync.aligned.m16n8k16.row.col.f32.f16.f16.f32 "
        "{%0,%1,%2,%3}, {%4,%5,%6,%7}, {%8,%9}, {%0,%1,%2,%3};"
        : "+f"(c[0]), "+f"(c[1]), "+f"(c[2]), "+f"(c[3])
        : "r"(a[0]), "r"(a[1]), "r"(a[2]), "r"(a[3]), "r"(b[0]), "r"(b[1]));
}

// ------------------------- edge preprocessing (self-detecting dtype) ---------
__global__ void k_edge_prep(const void* __restrict__ ei, const void* __restrict__ et,
                            const void* __restrict__ bt) {
    __shared__ int s_is64;
    if (threadIdx.x < 32) {
        const ull* p = (const ull*)ei;
        ull m = 0;
#pragma unroll
        for (int i = 0; i < 8; i++) {
            ull v = p[threadIdx.x + i * 32];
            m = v > m ? v : m;
        }
        unsigned any64 = __ballot_sync(0xffffffffu, m >= (1ull << 32));
        if (threadIdx.x == 0) s_is64 = (any64 == 0u) ? 1 : 0;
    }
    __syncthreads();
    int is64 = s_is64;
    int e = blockIdx.x * blockDim.x + threadIdx.x;
    if (e < E_EDGES) {
        int src, dst, ty;
        if (is64) {
            const long long* p = (const long long*)ei;
            src = (int)p[e]; dst = (int)p[E_EDGES + e];
            ty = (int)((const long long*)et)[e];
        } else {
            const int* p = (const int*)ei;
            src = p[e]; dst = p[E_EDGES + e];
            ty = ((const int*)et)[e];
        }
        g_src32[e] = src;
        int s = dst * R_REL + ty;
        g_segid[e] = s;
        atomicAdd(&g_hist[s], 1);
    }
    if (e < N_NODES)
        g_batch32[e] = is64 ? (int)((const long long*)bt)[e] : ((const int*)bt)[e];
}

__global__ void k_scan1() {
    __shared__ int sd[256];
    int t = threadIdx.x;
    int base = blockIdx.x * 1024 + t * 4;
    int v0 = 0, v1 = 0, v2 = 0, v3 = 0;
    if (base + 0 < NRSEG) v0 = g_hist[base + 0];
    if (base + 1 < NRSEG) v1 = g_hist[base + 1];
    if (base + 2 < NRSEG) v2 = g_hist[base + 2];
    if (base + 3 < NRSEG) v3 = g_hist[base + 3];
    int ts = v0 + v1 + v2 + v3;
    sd[t] = ts; __syncthreads();
    for (int off = 1; off < 256; off <<= 1) {
        int x = (t >= off) ? sd[t - off] : 0;
        __syncthreads();
        sd[t] += x;
        __syncthreads();
    }
    int ex = sd[t] - ts;
    if (base + 0 < NRSEG) g_segstart[base + 0] = ex;
    ex += v0; if (base + 1 < NRSEG) g_segstart[base + 1] = ex;
    ex += v1; if (base + 2 < NRSEG) g_segstart[base + 2] = ex;
    ex += v2; if (base + 3 < NRSEG) g_segstart[base + 3] = ex;
    if (t == 255) g_bsums[blockIdx.x] = sd[255];
}

__global__ void k_scan2(int nb) {
    __shared__ int sd[512];
    int t = threadIdx.x;
    int v = (t < nb) ? g_bsums[t] : 0;
    sd[t] = v; __syncthreads();
    for (int off = 1; off < 512; off <<= 1) {
        int x = (t >= off) ? sd[t - off] : 0;
        __syncthreads();
        sd[t] += x;
        __syncthreads();
    }
    if (t < nb) g_bsums[t] = sd[t] - v;
}

__global__ void k_scan3() {
    int i = blockIdx.x * blockDim.x + threadIdx.x;
    if (i < NRSEG) {
        int v = g_segstart[i] + g_bsums[i >> 10];
        g_segstart[i] = v;
        g_cursor[i] = v;
        int c = g_hist[i];
        g_inv[i] = 1.0f / (float)(c > 0 ? c : 1);
        g_hist[i] = 0;            // self-clear for next graph replay
    }
    if (i < 2 * HID) g_colstats[i] = 0.f;
    if (i == 0) { g_segstart[NRSEG] = E_EDGES; g_maxkey = 0u; g_sumexp = 0.f; }
}

__global__ void k_permute() {
    int e = blockIdx.x * blockDim.x + threadIdx.x;
    if (e < E_EDGES) {
        int s = g_segid[e];
        int pos = atomicAdd(&g_cursor[s], 1);
        g_srcsorted[pos] = g_src32[e];
    }
}

// ------------------------- aggregation (gathers fp16, sums fp32) ------------
__global__ void __launch_bounds__(256) k_aggregate(const __half* __restrict__ hsrc) {
    int warp = (blockIdx.x * blockDim.x + threadIdx.x) >> 5;
    int lane = threadIdx.x & 31;
    if (warp >= NRSEG) return;
    int beg = g_segstart[warp], end = g_segstart[warp + 1];
    float ax = 0.f, ay = 0.f, az = 0.f, aw = 0.f;
    for (int e = beg; e < end; e++) {
        int s = g_srcsorted[e];
        uint2 v = ((const uint2*)(hsrc + (size_t)s * 128))[lane];
        float2 f0 = __half22float2(*(__half2*)&v.x);
        float2 f1 = __half22float2(*(__half2*)&v.y);
        ax += f0.x; ay += f0.y; az += f1.x; aw += f1.y;
    }
    float inv = g_inv[warp];
    uint2 o;
    o.x = pk_h2(ax * inv, ay * inv);
    o.y = pk_h2(az * inv, aw * inv);
    ((uint2*)g_aggh)[(size_t)warp * 32 + lane] = o;
}

// ------------------------- fp32 -> fp16 --------------------------------------
__global__ void k_tohalf(const float* __restrict__ src, __half* __restrict__ dst, int total4) {
    int i = blockIdx.x * blockDim.x + threadIdx.x;
    if (i < total4) {
        float4 v = ((const float4*)src)[i];
        uint2 o;
        o.x = pk_h2(v.x, v.y);
        o.y = pk_h2(v.z, v.w);
        ((uint2*)dst)[i] = o;
    }
}

// ------------------------- weight prep ---------------------------------------
__global__ void k_wprep(const float* __restrict__ W, const float* __restrict__ root,
                        __half* __restrict__ bh) {
    int idx = blockIdx.x * blockDim.x + threadIdx.x;
    if (idx < 128 * 1152) {
        int c = idx / 1152, k = idx % 1152;
        float v = (k < 1024) ? W[((k >> 7) * 128 + (k & 127)) * 128 + c]
                             : root[(k - 1024) * 128 + c];
        bh[idx] = __float2half_rn(v);
    }
}

template <int K>
__global__ void k_cprep(const float* __restrict__ C, __half* __restrict__ bh,
                        __half* __restrict__ bl) {
    int idx = blockIdx.x * blockDim.x + threadIdx.x;
    if (idx < 128 * K) {
        int c = idx / K, k = idx % K;
        float v = C[k * 128 + c];
        __half h = __float2half_rn(v);
        bh[idx] = h;
        bl[idx] = __float2half_rn(v - __half2float(h));
    }
}

// A1 [128][64] -> transposed split [64][128]
__global__ void k_a1prep(const float* __restrict__ A1) {
    int idx = blockIdx.x * blockDim.x + threadIdx.x;
    if (idx < 64 * 128) {
        int j = idx / 128, k = idx % 128;
        float v = A1[k * 64 + j];
        __half h = __float2half_rn(v);
        g_a1thi[idx] = h;
        g_a1tlo[idx] = __float2half_rn(v - __half2float(h));
    }
}

// ------------------------- mma.sync GEMM -------------------------------------
// 128x128 CTA tile, 256 thr, warp grid 4(M)x2(N), warp tile 32x64.
// SPLIT=0: D = A*Bhi^T (1 product, 4-stage pipeline)
// SPLIT=1: D = A*Bhi^T + A*Blo^T (2 products, 2-stage)
// MODE 0: +BN stats, out=raw. MODE 1: out=emb fp32 + embh.
// MODE 2: A=[embh|gembh[batch]], lrelu, out=t1h. MODE 3: row-norm -> outf.
#define BKC 32
#define ROWB 80          // smem bytes per tile row (32 fp16 + 16B pad)
#define TILE_B 10240     // 128 * 80
#define CP 132           // staging row stride (floats)

template <int MODE, int KT, int SPLIT>
__global__ void __launch_bounds__(256, 2) k_mgemm(
    const __half* __restrict__ A, const __half* __restrict__ A2,
    const int* __restrict__ batch,
    const __half* __restrict__ Bhi, const __half* __restrict__ Blo,
    const float* __restrict__ bias,
    float* __restrict__ outf, __half* __restrict__ oh) {
    constexpr int NCH = KT / BKC;
    constexpr int STAGES = SPLIT ? 2 : 4;
    constexpr int SBUF = (SPLIT ? 3 : 2) * TILE_B;
    extern __shared__ __align__(16) char dsm[];
    __shared__ float s_bias[128];
    __shared__ float s_stat[256];

    int tid = threadIdx.x;
    int bm = blockIdx.x * 128;
    int wid = tid >> 5, lane = tid & 31;
    int mo = (wid & 3) * 32;
    int no = (wid >> 2) * 64;
    uint32_t sbase = smem_u32(dsm);

    if (tid < 128) s_bias[tid] = bias[tid];
    if (MODE == 0) s_stat[tid] = 0.f;

    float acc[2][8][4];
#pragma unroll
    for (int mi = 0; mi < 2; mi++)
#pragma unroll
        for (int j = 0; j < 8; j++)
#pragma unroll
            for (int q = 0; q < 4; q++) acc[mi][j][q] = 0.f;

    auto loadChunk = [&](int i) {
        int st = i % STAGES;
        uint32_t sb = sbase + (uint32_t)(st * SBUF);
        int k0 = i * BKC;
#pragma unroll
        for (int it = 0; it < 2; it++) {
            int idx = it * 256 + tid;
            int row = idx >> 2, seg = idx & 3;
            int n = bm + row;
            bool v = (n < N_NODES);
            int nn = v ? n : 0;
            const __half* pa;
            if (MODE <= 1) {
                pa = (k0 < 1024) ? A + (size_t)nn * 1024 + k0
                                 : A2 + (size_t)nn * 128 + (k0 - 1024);
            } else if (MODE == 2) {
                if (k0 < 128) pa = A + (size_t)nn * 128 + k0;
                else {
                    int g = v ? batch[nn] : 0;
                    pa = A2 + (size_t)g * 128 + (k0 - 128);
                }
            } else {
                pa = A + (size_t)nn * 128 + k0;
            }
            cp16(sb + (uint32_t)(row * ROWB + seg * 16), pa + seg * 8, v ? 16u : 0u);
            uint32_t db = sb + TILE_B + (uint32_t)(row * ROWB + seg * 16);
            cp16(db, Bhi + (size_t)row * KT + k0 + seg * 8, 16u);
            if (SPLIT)
                cp16(db + TILE_B, Blo + (size_t)row * KT + k0 + seg * 8, 16u);
        }
        cp_commit();
    };

#pragma unroll
    for (int i = 0; i < STAGES - 1 && i < NCH; i++) loadChunk(i);
    for (int i = 0; i < NCH; i++) {
        cp_wait<STAGES - 2>();
        __syncthreads();
        if (i + STAGES - 1 < NCH) loadChunk(i + STAGES - 1);
        uint32_t ab = sbase + (uint32_t)((i % STAGES) * SBUF);
#pragma unroll
        for (int kk = 0; kk < 2; kk++) {
            uint32_t a[2][4];
#pragma unroll
            for (int mi = 0; mi < 2; mi++) {
                uint32_t r = (uint32_t)(mo + mi * 16 + (lane & 15));
                uint32_t c = (uint32_t)(kk * 16 + (lane >> 4) * 8);
                ldm4(a[mi], ab + r * ROWB + c * 2);
            }
#pragma unroll
            for (int jp = 0; jp < 4; jp++) {
                uint32_t r = (uint32_t)(no + jp * 16 + (lane & 15));
                uint32_t c = (uint32_t)(kk * 16 + (lane >> 4) * 8);
                uint32_t bd = ab + TILE_B + r * ROWB + c * 2;
                uint32_t t[4];
                ldm4(t, bd);
                uint32_t bh0[2] = {t[0], t[2]}, bh1[2] = {t[1], t[3]};
#pragma unroll
                for (int mi = 0; mi < 2; mi++) {
                    mma16816(acc[mi][jp * 2 + 0], a[mi], bh0);
                    mma16816(acc[mi][jp * 2 + 1], a[mi], bh1);
                }
                if (SPLIT) {
                    uint32_t u[4];
                    ldm4(u, bd + TILE_B);
                    uint32_t bl0[2] = {u[0], u[2]}, bl1[2] = {u[1], u[3]};
#pragma unroll
                    for (int mi = 0; mi < 2; mi++) {
                        mma16816(acc[mi][jp * 2 + 0], a[mi], bl0);
                        mma16816(acc[mi][jp * 2 + 1], a[mi], bl1);
                    }
                }
            }
        }
    }
    __syncthreads();

    // ---- stage accumulators to smem ----
    float* Cs = (float*)dsm;
#pragma unroll
    for (int mi = 0; mi < 2; mi++)
#pragma unroll
        for (int j = 0; j < 8; j++) {
            int r0 = mo + mi * 16 + (lane >> 2);
            int col = no + j * 8 + (lane & 3) * 2;
            *(float2*)&Cs[r0 * CP + col] = make_float2(acc[mi][j][0], acc[mi][j][1]);
            *(float2*)&Cs[(r0 + 8) * CP + col] = make_float2(acc[mi][j][2], acc[mi][j][3]);
        }
    __syncthreads();

    // ---- per-row epilogue: threads 0..127 own row tid ----
    if (tid < 128) {
        int n = bm + tid;
        bool valid = (n < N_NODES);
        const float* crow = &Cs[tid * CP];

        if (MODE == 3) {
            float ss = 0.f;
#pragma unroll 8
            for (int c = 0; c < 128; c++) {
                float v = crow[c] + s_bias[c];
                ss += v * v;
            }
            float sc = 1.f / fmaxf(sqrtf(ss), 1e-12f);
            if (valid) {
#pragma unroll
                for (int c4 = 0; c4 < 32; c4++) {
                    float4 o;
                    o.x = (crow[c4 * 4 + 0] + s_bias[c4 * 4 + 0]) * sc;
                    o.y = (crow[c4 * 4 + 1] + s_bias[c4 * 4 + 1]) * sc;
                    o.z = (crow[c4 * 4 + 2] + s_bias[c4 * 4 + 2]) * sc;
                    o.w = (crow[c4 * 4 + 3] + s_bias[c4 * 4 + 3]) * sc;
                    *(float4*)&outf[(size_t)n * 128 + c4 * 4] = o;
                }
            }
        } else {
#pragma unroll
            for (int cb = 0; cb < 4; cb++) {
                float vf[32];
#pragma unroll
                for (int j = 0; j < 32; j++) {
                    float v = crow[cb * 32 + j] + s_bias[cb * 32 + j];
                    if (MODE == 2) v = lrelu(v);
                    vf[j] = v;
                }
                if (MODE == 0) {
#pragma unroll
                    for (int j = 0; j < 32; j++) {
                        float a_ = valid ? vf[j] : 0.f;
                        float q_ = valid ? vf[j] * vf[j] : 0.f;
#pragma unroll
                        for (int off = 16; off > 0; off >>= 1) {
                            a_ += __shfl_xor_sync(0xffffffffu, a_, off);
                            q_ += __shfl_xor_sync(0xffffffffu, q_, off);
                        }
                        if ((tid & 31) == 0) {
                            atomicAdd(&s_stat[cb * 32 + j], a_);
                            atomicAdd(&s_stat[128 + cb * 32 + j], q_);
                        }
                    }
                }
                if (valid) {
                    if (MODE == 0 || MODE == 1) {
#pragma unroll
                        for (int j4 = 0; j4 < 8; j4++)
                            *(float4*)&outf[(size_t)n * 128 + cb * 32 + j4 * 4] =
                                make_float4(vf[j4 * 4], vf[j4 * 4 + 1], vf[j4 * 4 + 2], vf[j4 * 4 + 3]);
                    }
                    if (MODE == 1 || MODE == 2) {
                        uint32_t* ph = (uint32_t*)(oh + (size_t)n * 128 + cb * 32);
#pragma unroll
                        for (int j2 = 0; j2 < 16; j2++)
                            ph[j2] = pk_h2(vf[j2 * 2], vf[j2 * 2 + 1]);
                    }
                }
            }
        }
    }
    __syncthreads();
    if (MODE == 0 && tid < 256) atomicAdd(&g_colstats[tid], s_stat[tid]);
}

// ------------------------- BN ------------------------------------------------
__global__ void k_bnfin(const float* __restrict__ gamma, const float* __restrict__ beta) {
    int c = threadIdx.x;
    if (c < HID) {
        float inv_n = 1.f / (float)N_NODES;
        float mu = g_colstats[c] * inv_n;
        float var = fmaxf(g_colstats[HID + c] * inv_n - mu * mu, 0.f);
        float sc = gamma[c] * rsqrtf(var + EPS_BN);
        g_bnscale[c] = sc;
        g_bnshift[c] = beta[c] - mu * sc;
        g_colstats[c] = 0.f;           // re-arm for next layer / replay
        g_colstats[HID + c] = 0.f;
    }
}

__global__ void k_bnapply() {
    int i = blockIdx.x * blockDim.x + threadIdx.x;
    if (i < N_NODES * 32) {
        float4 v = ((const float4*)g_raw)[i];
        int c4 = i & 31;
        float4 sc = ((const float4*)g_bnscale)[c4];
        float4 sh = ((const float4*)g_bnshift)[c4];
        float ox = lrelu(v.x * sc.x + sh.x);
        float oy = lrelu(v.y * sc.y + sh.y);
        float oz = lrelu(v.z * sc.z + sh.z);
        float ow = lrelu(v.w * sc.w + sh.w);
        uint2 o;
        o.x = pk_h2(ox, oy);
        o.y = pk_h2(oz, ow);
        ((uint2*)g_hh)[i] = o;
    }
}

// ------------------------- attention scores (tensor cores) -------------------
// scores = lrelu(embh @ A1 + a1) @ A2 + a2 ; also global max via atomicMax.
// CTA: 128 rows x 64 cols, K=128, A1 2-product split. 256 thr, warps 4(M)x2(N).
#define SROWB 272          // 128 fp16 + 16B pad
#define SAT 34816          // 128 * 272 (A tile bytes)
#define SBT 17408          // 64 * 272  (B tile bytes)
#define SCP 68             // staging stride floats

__global__ void __launch_bounds__(256, 2) k_scoresT(
    const float* __restrict__ a1, const float* __restrict__ A2v,
    const float* __restrict__ a2v) {
    extern __shared__ __align__(16) char dsm[];
    __shared__ float s_a1[64];
    __shared__ float s_A2[64];
    __shared__ unsigned s_bmax;
    int tid = threadIdx.x;
    int bm = blockIdx.x * 128;
    int wid = tid >> 5, lane = tid & 31;
    int mo = (wid & 3) * 32;
    int no = (wid >> 2) * 32;
    uint32_t sbase = smem_u32(dsm);

    if (tid < 64) { s_a1[tid] = a1[tid]; s_A2[tid] = A2v[tid]; }
    if (tid == 0) s_bmax = 0u;

    // load A tile (embh rows, zero-fill OOB)
#pragma unroll
    for (int it = 0; it < 8; it++) {
        int idx = it * 256 + tid;
        int row = idx >> 4, seg = idx & 15;
        int n = bm + row;
        bool v = (n < N_NODES);
        cp16(sbase + (uint32_t)(row * SROWB + seg * 16),
             g_embh + (size_t)(v ? n : 0) * 128 + seg * 8, v ? 16u : 0u);
    }
    // load B tiles (A1^T hi/lo, 64 rows x 128)
#pragma unroll
    for (int it = 0; it < 4; it++) {
        int idx = it * 256 + tid;
        int row = idx >> 4, seg = idx & 15;
        uint32_t db = sbase + SAT + (uint32_t)(row * SROWB + seg * 16);
        cp16(db, g_a1thi + (size_t)row * 128 + seg * 8, 16u);
        cp16(db + SBT, g_a1tlo + (size_t)row * 128 + seg * 8, 16u);
    }
    cp_commit();
    cp_wait<0>();
    __syncthreads();

    float acc[2][4][4];
#pragma unroll
    for (int mi = 0; mi < 2; mi++)
#pragma unroll
        for (int j = 0; j < 4; j++)
#pragma unroll
            for (int q = 0; q < 4; q++) acc[mi][j][q] = 0.f;

#pragma unroll
    for (int kk = 0; kk < 8; kk++) {
        uint32_t a[2][4];
#pragma unroll
        for (int mi = 0; mi < 2; mi++) {
            uint32_t r = (uint32_t)(mo + mi * 16 + (lane & 15));
            uint32_t c = (uint32_t)(kk * 16 + (lane >> 4) * 8);
            ldm4(a[mi], sbase + r * SROWB + c * 2);
        }
#pragma unroll
        for (int jn = 0; jn < 2; jn++) {
            uint32_t r = (uint32_t)(no + jn * 16 + (lane & 15));
            uint32_t c = (uint32_t)(kk * 16 + (lane >> 4) * 8);
            uint32_t bd = sbase + SAT + r * SROWB + c * 2;
            uint32_t t[4], u[4];
            ldm4(t, bd);
            ldm4(u, bd + SBT);
            uint32_t bh0[2] = {t[0], t[2]}, bh1[2] = {t[1], t[3]};
            uint32_t bl0[2] = {u[0], u[2]}, bl1[2] = {u[1], u[3]};
#pragma unroll
            for (int mi = 0; mi < 2; mi++) {
                mma16816(acc[mi][jn * 2 + 0], a[mi], bh0);
                mma16816(acc[mi][jn * 2 + 0], a[mi], bl0);
                mma16816(acc[mi][jn * 2 + 1], a[mi], bh1);
                mma16816(acc[mi][jn * 2 + 1], a[mi], bl1);
            }
        }
    }
    __syncthreads();

    // stage 128x64 to smem
    float* Cs = (float*)dsm;
#pragma unroll
    for (int mi = 0; mi < 2; mi++)
#pragma unroll
        for (int j = 0; j < 4; j++) {
            int r0 = mo + mi * 16 + (lane >> 2);
            int col = no + j * 8 + (lane & 3) * 2;
            *(float2*)&Cs[r0 * SCP + col] = make_float2(acc[mi][j][0], acc[mi][j][1]);
            *(float2*)&Cs[(r0 + 8) * SCP + col] = make_float2(acc[mi][j][2], acc[mi][j][3]);
        }
    __syncthreads();

    if (tid < 128) {
        int n = bm + tid;
        bool valid = (n < N_NODES);
        const float* crow = &Cs[tid * SCP];
        float s = 0.f;
#pragma unroll 8
        for (int j = 0; j < 64; j++)
            s += lrelu(crow[j] + s_a1[j]) * s_A2[j];
        float score = s + a2v[0];
        unsigned key = valid ? enc_f(score) : 0u;
        if (valid) g_scores[n] = score;
#pragma unroll
        for (int off = 16; off > 0; off >>= 1) {
            unsigned o = __shfl_xor_sync(0xffffffffu, key, off);
            key = o > key ? o : key;
        }
        if ((tid & 31) == 0) atomicMax(&s_bmax, key);
    }
    __syncthreads();
    if (tid == 0) atomicMax(&g_maxkey, s_bmax);
}

__global__ void k_sumexp() {
    __shared__ float sred[256];
    int n = blockIdx.x * blockDim.x + threadIdx.x;
    float gmax = dec_f(g_maxkey);
    float v = (n < N_NODES) ? expf(g_scores[n] - gmax) : 0.f;
    sred[threadIdx.x] = v;
    __syncthreads();
    for (int off = 128; off > 0; off >>= 1) {
        if (threadIdx.x < off) sred[threadIdx.x] += sred[threadIdx.x + off];
        __syncthreads();
    }
    if (threadIdx.x == 0) atomicAdd(&g_sumexp, sred[0]);
}

__global__ void k_gbounds() {
    int i = blockIdx.x * blockDim.x + threadIdx.x;
    if (i <= N_NODES) {
        int cur = (i < N_NODES) ? g_batch32[i] : NG;
        int prev = (i == 0) ? -1 : g_batch32[i - 1];
        for (int g = prev + 1; g <= cur && g <= NG; g++) g_gstart[g] = i;
    }
}

// pool: 256 thr = 8 node-lanes x 32 col-threads, coalesced, fused softmax.
__global__ void __launch_bounds__(256) k_pool() {
    __shared__ float s_red[8][128];
    int g = blockIdx.x;
    int ty = threadIdx.x >> 5, tx = threadIdx.x & 31;
    float gmax = dec_f(g_maxkey);
    float invs = 1.f / g_sumexp;
    int b = g_gstart[g], e = g_gstart[g + 1];
    float4 acc = make_float4(0.f, 0.f, 0.f, 0.f);
    for (int n = b + ty; n < e; n += 8) {
        float w = expf(g_scores[n] - gmax) * invs;
        float4 v = *(const float4*)&g_emb[(size_t)n * 128 + tx * 4];
        acc.x += v.x * w; acc.y += v.y * w; acc.z += v.z * w; acc.w += v.w * w;
    }
    *(float4*)&s_red[ty][tx * 4] = acc;
    __syncthreads();
    if (threadIdx.x < 128) {
        int c = threadIdx.x;
        float s = 0.f;
#pragma unroll
        for (int t = 0; t < 8; t++) s += s_red[t][c];
        g_gembh[g * 128 + c] = __float2half_rn(s);
    }
}

// ------------------------- host launcher --------------------------------------
extern "C" void kernel_launch(void* const* d_in, const int* in_sizes, int n_in,
                              void* d_out, int out_size) {
    const float* x     = (const float*)d_in[0];
    const void*  ei    = d_in[1];
    const void*  et    = d_in[2];
    const void*  bt    = d_in[3];
    const float* W1    = (const float*)d_in[4];
    const float* root1 = (const float*)d_in[5];
    const float* b1    = (const float*)d_in[6];
    const float* W2    = (const float*)d_in[7];
    const float* root2 = (const float*)d_in[8];
    const float* b2    = (const float*)d_in[9];
    const float* W3    = (const float*)d_in[10];
    const float* root3 = (const float*)d_in[11];
    const float* b3    = (const float*)d_in[12];
    const float* g1    = (const float*)d_in[13];
    const float* beta1 = (const float*)d_in[14];
    const float* g2    = (const float*)d_in[15];
    const float* beta2 = (const float*)d_in[16];
    const float* A1    = (const float*)d_in[17];
    const float* a1    = (const float*)d_in[18];
    const float* A2    = (const float*)d_in[19];
    const float* a2    = (const float*)d_in[20];
    const float* C1    = (const float*)d_in[21];
    const float* c1    = (const float*)d_in[22];
    const float* C2    = (const float*)d_in[23];
    const float* c2    = (const float*)d_in[24];
    float* out = (float*)d_out;

    void* p;
    cudaGetSymbolAddress(&p, g_aggh);   __half* aggh = (__half*)p;
    cudaGetSymbolAddress(&p, g_raw);    float* raw  = (float*)p;
    cudaGetSymbolAddress(&p, g_emb);    float* emb  = (float*)p;
    cudaGetSymbolAddress(&p, g_xh);     __half* xh = (__half*)p;
    cudaGetSymbolAddress(&p, g_hh);     __half* hh = (__half*)p;
    cudaGetSymbolAddress(&p, g_embh);   __half* embh = (__half*)p;
    cudaGetSymbolAddress(&p, g_t1h);    __half* t1h = (__half*)p;
    cudaGetSymbolAddress(&p, g_gembh);  __half* gembh = (__half*)p;
    cudaGetSymbolAddress(&p, g_w1hi);   __half* w1hi = (__half*)p;
    cudaGetSymbolAddress(&p, g_w2hi);   __half* w2hi = (__half*)p;
    cudaGetSymbolAddress(&p, g_w3hi);   __half* w3hi = (__half*)p;
    cudaGetSymbolAddress(&p, g_c1hi);   __half* c1hi = (__half*)p;
    cudaGetSymbolAddress(&p, g_c1lo);   __half* c1lo = (__half*)p;
    cudaGetSymbolAddress(&p, g_c2hi);   __half* c2hi = (__half*)p;
    cudaGetSymbolAddress(&p, g_c2lo);   __half* c2lo = (__half*)p;
    cudaGetSymbolAddress(&p, g_batch32); int* batch32 = (int*)p;

    const int DSM0 = 4 * 2 * TILE_B;            // 81920 (1-product, 4 stages)
    const int DSM1 = 128 * CP * 4;              // 67584 (2-product + staging)
    const int DSMS = SAT + 2 * SBT;             // 69632 (scores)
    cudaFuncSetAttribute(k_mgemm<0, 1152, 0>, cudaFuncAttributeMaxDynamicSharedMemorySize, DSM0);
    cudaFuncSetAttribute(k_mgemm<1, 1152, 0>, cudaFuncAttributeMaxDynamicSharedMemorySize, DSM0);
    cudaFuncSetAttribute(k_mgemm<2, 256, 1>,  cudaFuncAttributeMaxDynamicSharedMemorySize, DSM1);
    cudaFuncSetAttribute(k_mgemm<3, 128, 1>,  cudaFuncAttributeMaxDynamicSharedMemorySize, DSM1);
    cudaFuncSetAttribute(k_scoresT, cudaFuncAttributeMaxDynamicSharedMemorySize, DSMS);

    const int NB1 = (NRSEG + 1023) / 1024;

    k_edge_prep<<<(E_EDGES + 255) / 256, 256>>>(ei, et, bt);
    k_scan1<<<NB1, 256>>>();
    k_scan2<<<1, 512>>>(NB1);
    k_scan3<<<(NRSEG + 255) / 256, 256>>>();
    k_permute<<<(E_EDGES + 255) / 256, 256>>>();

    k_wprep<<<(128 * 1152 + 255) / 256, 256>>>(W1, root1, w1hi);
    k_wprep<<<(128 * 1152 + 255) / 256, 256>>>(W2, root2, w2hi);
    k_wprep<<<(128 * 1152 + 255) / 256, 256>>>(W3, root3, w3hi);
    k_cprep<256><<<(128 * 256 + 255) / 256, 256>>>(C1, c1hi, c1lo);
    k_cprep<128><<<(128 * 128 + 255) / 256, 256>>>(C2, c2hi, c2lo);
    k_a1prep<<<(64 * 128 + 255) / 256, 256>>>(A1);
    k_tohalf<<<(N_NODES * 32 + 255) / 256, 256>>>(x, xh, N_NODES * 32);

    const int GB = (N_NODES + 127) / 128;   // 391
    const int AGG_BLOCKS = NRSEG / 8;       // 50000

    // layer 1
    k_aggregate<<<AGG_BLOCKS, 256>>>(xh);
    k_mgemm<0, 1152, 0><<<GB, 256, DSM0>>>(aggh, xh, nullptr, w1hi, nullptr, b1, raw, nullptr);
    k_bnfin<<<1, 128>>>(g1, beta1);
    k_bnapply<<<(N_NODES * 32 + 255) / 256, 256>>>();

    // layer 2
    k_aggregate<<<AGG_BLOCKS, 256>>>(hh);
    k_mgemm<0, 1152, 0><<<GB, 256, DSM0>>>(aggh, hh, nullptr, w2hi, nullptr, b2, raw, nullptr);
    k_bnfin<<<1, 128>>>(g2, beta2);
    k_bnapply<<<(N_NODES * 32 + 255) / 256, 256>>>();

    // layer 3
    k_aggregate<<<AGG_BLOCKS, 256>>>(hh);
    k_mgemm<1, 1152, 0><<<GB, 256, DSM0>>>(aggh, hh, nullptr, w3hi, nullptr, b3, emb, embh);

    // attention pooling (tensor-core scores, fused softmax pool)
    k_scoresT<<<GB, 256, DSMS>>>(a1, A2, a2);
    k_sumexp<<<(N_NODES + 255) / 256, 256>>>();
    k_gbounds<<<(N_NODES + 256) / 256, 256>>>();
    k_pool<<<NG, 256>>>();

    // combiner MLP (2-product split) + row normalize
    k_mgemm<2, 256, 1><<<GB, 256, DSM1>>>(embh, gembh, batch32, c1hi, c1lo, c1, nullptr, t1h);
    k_mgemm<3, 128, 1><<<GB, 256, DSM1>>>(t1h, nullptr, nullptr, c2hi, c2lo, c2, out, nullptr);

    (void)in_sizes; (void)n_in; (void)out_size;
}